// round 13
// baseline (speedup 1.0000x reference)
#include <cuda_runtime.h>
#include <cuda_fp16.h>
#include <cstdint>

#define BATCH 8
#define NPTS  16384
#define SPTS  2048
#define C1D   128
#define C2D   256
#define K0D   384      // C1+C2
#define OD    256      // both MLP widths
#define M_TOT (BATCH*NPTS)   // 131072
#define BN_EPS 1e-5f
#define NSLOT 8

// GEMM tiling: BM=128, BN=256(=OD), BK=16, 512 threads, 3-stage, 48KB static smem
#define BM 128
#define BN 256
#define BK 16
#define PITCH 32
#define TILE  (128*PITCH)              // 4096 B
#define STAGE (4*TILE)                 // Ah,Al (2 tiles) + B 256 rows (2 tiles) = 16KB
#define SMEMB (3*STAGE)                // 49152 = 48KB

// ---------------- scratch (static device globals; no allocation) ----------------
__device__ __align__(16) float g_p2t[BATCH * SPTS * C2D];
__device__ __align__(16) float g_ht [(size_t)M_TOT * C1D];   // fp32 h tail (p1 part)
__device__ __align__(16) float g_y0 [(size_t)M_TOT * OD];
__device__ __align__(16) float g_y1 [(size_t)M_TOT * OD];
__device__ __align__(16) __half g_w0h[OD * K0D];
__device__ __align__(16) __half g_w1h[OD * OD];
__device__ int   g_idx[M_TOT * 3];
__device__ float g_w  [M_TOT * 3];
__device__ float g_sum0[NSLOT * OD], g_sq0[NSLOT * OD];
__device__ float g_sum1[NSLOT * OD], g_sq1[NSLOT * OD];
__device__ __align__(16) float g_sc0[OD];
__device__ __align__(16) float g_sh0[OD];
__device__ __align__(16) float g_sc1[OD];
__device__ __align__(16) float g_sh1[OD];

// ---------------- asm helpers --------------------------------------------------
__device__ __forceinline__ uint32_t s2u(const void* p) {
    uint32_t a;
    asm("{ .reg .u64 t; cvta.to.shared.u64 t, %1; cvt.u32.u64 %0, t; }" : "=r"(a) : "l"(p));
    return a;
}
__device__ __forceinline__ void cp16(uint32_t s, const void* g) {
    asm volatile("cp.async.cg.shared.global [%0], [%1], 16;" :: "r"(s), "l"(g));
}
#define LDX4(r, addr)                                                          \
    asm volatile("ldmatrix.sync.aligned.m8n8.x4.shared.b16 {%0,%1,%2,%3}, [%4];" \
        : "=r"((r)[0]), "=r"((r)[1]), "=r"((r)[2]), "=r"((r)[3]) : "r"(addr))
#define MMA(d, a, b0, b1)                                                      \
    asm volatile("mma.sync.aligned.m16n8k16.row.col.f32.f16.f16.f32 "          \
        "{%0,%1,%2,%3}, {%4,%5,%6,%7}, {%8,%9}, {%0,%1,%2,%3};"                \
        : "+f"((d)[0]), "+f"((d)[1]), "+f"((d)[2]), "+f"((d)[3])               \
        : "r"((a)[0]), "r"((a)[1]), "r"((a)[2]), "r"((a)[3]), "r"(b0), "r"(b1))

__device__ __forceinline__ uint2 split_h4(float4 v) {
    __half2 a, b;
    a.x = __float2half_rn(v.x); a.y = __float2half_rn(v.y);
    b.x = __float2half_rn(v.z); b.y = __float2half_rn(v.w);
    uint2 r; r.x = *(uint32_t*)&a; r.y = *(uint32_t*)&b;
    return r;
}
__device__ __forceinline__ uint2 split_l4(float4 v) {
    __half hx = __float2half_rn(v.x), hy = __float2half_rn(v.y);
    __half hz = __float2half_rn(v.z), hw = __float2half_rn(v.w);
    __half2 a, b;
    a.x = __float2half_rn(v.x - __half2float(hx));
    a.y = __float2half_rn(v.y - __half2float(hy));
    b.x = __float2half_rn(v.z - __half2float(hz));
    b.y = __float2half_rn(v.w - __half2float(hw));
    uint2 r; r.x = *(uint32_t*)&a; r.y = *(uint32_t*)&b;
    return r;
}

// ---------------- kernel: zero BN accumulators ---------------------------------
__global__ void k_zero() {
    int t = blockIdx.x * blockDim.x + threadIdx.x;
    if (t < NSLOT * OD) { g_sum0[t] = 0.f; g_sq0[t] = 0.f; g_sum1[t] = 0.f; g_sq1[t] = 0.f; }
}

// ---------------- kernel: round W to fp16 --------------------------------------
__global__ void k_wsplit(const float* __restrict__ W0, const float* __restrict__ W1) {
    int t = blockIdx.x * blockDim.x + threadIdx.x;
    if (t < OD * K0D) g_w0h[t] = __float2half_rn(W0[t]);
    if (t < OD * OD)  g_w1h[t] = __float2half_rn(W1[t]);
}

// ---------------- kernel: 3-NN + inverse-distance weights ----------------------
// Per-candidate distance math bit-identical to reference path; 4-wide guard.
__device__ __forceinline__ void nn_ins(float d, int s,
    float& d0, float& d1, float& d2, int& i0, int& i1, int& i2) {
    if (d < d2) {
        if (d < d1) {
            d2 = d1; i2 = i1;
            if (d < d0) { d1 = d0; i1 = i0; d0 = d; i0 = s; }
            else        { d1 = d;  i1 = s; }
        } else { d2 = d; i2 = s; }
    }
}
__global__ void k_nn3(const float* __restrict__ xyz1, const float* __restrict__ xyz2) {
    __shared__ float4 sp[SPTS];
    int b = blockIdx.y;
    const float* x2 = xyz2 + (size_t)b * SPTS * 3;
    for (int i = threadIdx.x; i < SPTS * 3; i += blockDim.x) {
        int s = i / 3, d = i - 3 * s;
        ((float*)&sp[s])[d] = x2[i];
    }
    __syncthreads();

    int n = blockIdx.x * blockDim.x + threadIdx.x;
    const float* p = xyz1 + ((size_t)b * NPTS + n) * 3;
    float px = p[0], py = p[1], pz = p[2];

    float d0 = 1e30f, d1 = 1e30f, d2 = 1e30f;
    int   i0 = 0,     i1 = 0,     i2 = 0;
    #pragma unroll 1
    for (int s = 0; s < SPTS; s += 4) {
        float4 q0 = sp[s], q1 = sp[s + 1], q2 = sp[s + 2], q3 = sp[s + 3];
        float dx = px - q0.x, dy = py - q0.y, dz = pz - q0.z;
        float da = fmaf(dx, dx, fmaf(dy, dy, dz * dz));
        dx = px - q1.x; dy = py - q1.y; dz = pz - q1.z;
        float db = fmaf(dx, dx, fmaf(dy, dy, dz * dz));
        dx = px - q2.x; dy = py - q2.y; dz = pz - q2.z;
        float dc = fmaf(dx, dx, fmaf(dy, dy, dz * dz));
        dx = px - q3.x; dy = py - q3.y; dz = pz - q3.z;
        float dd = fmaf(dx, dx, fmaf(dy, dy, dz * dz));
        float mn = fminf(fminf(da, db), fminf(dc, dd));
        if (mn < d2) {
            nn_ins(da, s,     d0, d1, d2, i0, i1, i2);
            nn_ins(db, s + 1, d0, d1, d2, i0, i1, i2);
            nn_ins(dc, s + 2, d0, d1, d2, i0, i1, i2);
            nn_ins(dd, s + 3, d0, d1, d2, i0, i1, i2);
        }
    }
    d0 = fmaxf(d0, 1e-10f); d1 = fmaxf(d1, 1e-10f); d2 = fmaxf(d2, 1e-10f);
    float w0 = 1.f / d0, w1 = 1.f / d1, w2 = 1.f / d2;
    float inv = 1.f / (w0 + w1 + w2);
    int base = ((b * NPTS) + n) * 3;
    g_idx[base] = i0; g_idx[base + 1] = i1; g_idx[base + 2] = i2;
    g_w[base] = w0 * inv; g_w[base + 1] = w1 * inv; g_w[base + 2] = w2 * inv;
}

// ---------------- transpose points2 [b,c,s] -> [b,s,c] -------------------------
__global__ void k_tr_p2(const float* __restrict__ p2) {
    __shared__ float tile[32][33];
    int b = blockIdx.z;
    int c0 = blockIdx.y * 32, s0 = blockIdx.x * 32;
    int tx = threadIdx.x, ty = threadIdx.y;
    #pragma unroll
    for (int i = 0; i < 32; i += 8)
        tile[ty + i][tx] = p2[((size_t)(b * C2D + c0 + ty + i)) * SPTS + s0 + tx];
    __syncthreads();
    #pragma unroll
    for (int i = 0; i < 32; i += 8)
        g_p2t[((size_t)(b * SPTS + s0 + ty + i)) * C2D + c0 + tx] = tile[tx][ty + i];
}

// ---------------- points1 [b,c,n] -> g_ht (fp32, 128 cols) ---------------------
__global__ void k_tr_p1(const float* __restrict__ p1) {
    __shared__ float tile[32][33];
    int b = blockIdx.z;
    int c0 = blockIdx.y * 32, n0 = blockIdx.x * 32;
    int tx = threadIdx.x, ty = threadIdx.y;
    #pragma unroll
    for (int i = 0; i < 32; i += 8)
        tile[ty + i][tx] = p1[((size_t)(b * C1D + c0 + ty + i)) * NPTS + n0 + tx];
    __syncthreads();
    #pragma unroll
    for (int i = 0; i < 32; i += 8)
        g_ht[((size_t)(b * NPTS + n0 + ty + i)) * C1D + c0 + tx] = tile[tx][ty + i];
}

// ---------------- shared GEMM pieces -------------------------------------------
__device__ __forceinline__ void gemm_epilogue(
    char* sm, int tid, int lane, int wm, int wn, int bx,
    float (*acc)[8][4], float* C, float* GS, float* GQ)
{
    float* ssum = (float*)sm;
    float* ssq  = ((float*)sm) + BN;
    if (tid < BN) { ssum[tid] = 0.f; ssq[tid] = 0.f; }
    __syncthreads();

    int rbase = bx * BM + wm * 32 + (lane >> 2);
    int cbase = wn * 64 + (lane & 3) * 2;
    #pragma unroll
    for (int mf = 0; mf < 2; ++mf)
        #pragma unroll
        for (int g = 0; g < 8; ++g) {
            *(float2*)(C + (size_t)(rbase + mf * 16) * OD + cbase + g * 8) =
                make_float2(acc[mf][g][0], acc[mf][g][1]);
            *(float2*)(C + (size_t)(rbase + mf * 16 + 8) * OD + cbase + g * 8) =
                make_float2(acc[mf][g][2], acc[mf][g][3]);
        }

    #pragma unroll
    for (int g = 0; g < 8; ++g)
        #pragma unroll
        for (int e = 0; e < 2; ++e) {
            float v0 = acc[0][g][e], v1 = acc[0][g][e + 2];
            float v2 = acc[1][g][e], v3 = acc[1][g][e + 2];
            float s = v0 + v1 + v2 + v3;
            float q = fmaf(v0, v0, fmaf(v1, v1, fmaf(v2, v2, v3 * v3)));
            #pragma unroll
            for (int m = 4; m < 32; m <<= 1) {
                s += __shfl_xor_sync(0xffffffffu, s, m);
                q += __shfl_xor_sync(0xffffffffu, q, m);
            }
            if ((lane >> 2) == 0) {
                int col = cbase + g * 8 + e;
                atomicAdd(&ssum[col], s);
                atomicAdd(&ssq[col], q);
            }
        }
    __syncthreads();
    if (tid < BN) {
        int slot = (bx & (NSLOT - 1)) * OD + tid;
        atomicAdd(&GS[slot], ssum[tid]);
        atomicAdd(&GQ[slot], ssq[tid]);
    }
}

#define COMPUTE_TILE(s0)                                                       \
    do {                                                                       \
        uint32_t ah[2][4], al[2][4];                                           \
        _Pragma("unroll")                                                      \
        for (int mf = 0; mf < 2; ++mf) {                                       \
            uint32_t aa = (s0) + a_off + mf * 16 * PITCH;                      \
            LDX4(ah[mf], aa);                                                  \
            LDX4(al[mf], aa + TILE);                                           \
        }                                                                      \
        _Pragma("unroll")                                                      \
        for (int g = 0; g < 4; ++g) {                                          \
            uint32_t ba = (s0) + 2 * TILE + b_off + g * 16 * PITCH;            \
            uint32_t bb[4];                                                    \
            LDX4(bb, ba);                                                      \
            _Pragma("unroll")                                                  \
            for (int mf = 0; mf < 2; ++mf) {                                   \
                MMA(acc[mf][2 * g],     ah[mf], bb[0], bb[2]);                 \
                MMA(acc[mf][2 * g + 1], ah[mf], bb[1], bb[3]);                 \
                MMA(acc[mf][2 * g],     al[mf], bb[0], bb[2]);                 \
                MMA(acc[mf][2 * g + 1], al[mf], bb[1], bb[3]);                 \
            }                                                                  \
        }                                                                      \
    } while (0)

// ---------------- GEMM0: interp FUSED into A-load -------------------------------
// A row m: cols [0,256) = w0*p2t[i0] + w1*p2t[i1] + w2*p2t[i2] (L2-resident
// gather), cols [256,384) = g_ht. fp16 hi/lo split in regs, STS to smem;
// B via 3-stage cp.async.
__global__ __launch_bounds__(512) void k_gemm0()
{
    constexpr int KT = K0D / BK;   // 24
    __shared__ __align__(16) char sm[SMEMB];
    uint32_t sb = s2u(sm);
    int tid = threadIdx.x, bx = blockIdx.x;
    int wid = tid >> 5, lane = tid & 31;
    int wm = wid & 3, wn = wid >> 2;

    float acc[2][8][4];
    #pragma unroll
    for (int a = 0; a < 2; ++a)
        #pragma unroll
        for (int b = 0; b < 8; ++b)
            #pragma unroll
            for (int c = 0; c < 4; ++c) acc[a][b][c] = 0.f;

    uint32_t sw16 = (uint32_t)((((lane >> 4) ^ (lane >> 2)) & 1) << 4);
    uint32_t a_off = (wm * 32 + (lane & 15)) * PITCH + sw16;
    uint32_t b_off = (wn * 64 + (lane & 15)) * PITCH + sw16;

    // A fused-interp per-thread state: one row, 4 k per stage
    int arow = tid >> 2, akq = tid & 3;
    int m = bx * BM + arow;
    int pb = m >> 14;                   // batch (NPTS = 2^14)
    int nbase = m * 3;
    int i0 = g_idx[nbase], i1 = g_idx[nbase + 1], i2 = g_idx[nbase + 2];
    float w0 = g_w[nbase], w1 = g_w[nbase + 1], w2 = g_w[nbase + 2];
    const float4* r0 = (const float4*)(g_p2t + ((size_t)pb * SPTS + i0) * C2D);
    const float4* r1 = (const float4*)(g_p2t + ((size_t)pb * SPTS + i1) * C2D);
    const float4* r2 = (const float4*)(g_p2t + ((size_t)pb * SPTS + i2) * C2D);
    const float4* ht = (const float4*)(g_ht + (size_t)m * C1D);
    int aswz = (akq >> 1) ^ ((arow >> 2) & 1);
    uint32_t aoffb = (uint32_t)(arow * PITCH + aswz * 16 + (akq & 1) * 8);

    #define LOADA0(kt_, dst_)                                                  \
        do {                                                                   \
            int c4 = (kt_) * 4 + akq;                                          \
            if ((kt_) < 16) {                                                  \
                float4 va = r0[c4], vb = r1[c4], vc = r2[c4];                  \
                dst_.x = w0 * va.x + w1 * vb.x + w2 * vc.x;                    \
                dst_.y = w0 * va.y + w1 * vb.y + w2 * vc.y;                    \
                dst_.z = w0 * va.z + w1 * vb.z + w2 * vc.z;                    \
                dst_.w = w0 * va.w + w1 * vb.w + w2 * vc.w;                    \
            } else {                                                           \
                dst_ = ht[((kt_) - 16) * 4 + akq];                             \
            }                                                                  \
        } while (0)

    // prologue: A stages 0,1 + B stages 0,1
    float4 rA0, rA;
    LOADA0(0, rA0);
    LOADA0(1, rA);
    *(uint2*)(sm + aoffb)        = split_h4(rA0);
    *(uint2*)(sm + TILE + aoffb) = split_l4(rA0);
    {
        int row = tid >> 1, ch = tid & 1;
        int sw = ch ^ ((row >> 2) & 1);
        uint32_t d = sb + 2 * TILE + row * PITCH + sw * 16;
        cp16(d, (const char*)(g_w0h + (size_t)row * K0D + 0 * BK) + ch * 16);
        asm volatile("cp.async.commit_group;" ::: "memory");
        cp16(d + STAGE, (const char*)(g_w0h + (size_t)row * K0D + 1 * BK) + ch * 16);
        asm volatile("cp.async.commit_group;" ::: "memory");
    }

    int st = 0;
    for (int kt = 0; kt < KT; ++kt) {
        if (kt + 1 < KT) asm volatile("cp.async.wait_group 1;" ::: "memory");
        else             asm volatile("cp.async.wait_group 0;" ::: "memory");
        __syncthreads();

        if (kt + 2 < KT) {
            int st2 = st + 2; if (st2 >= 3) st2 -= 3;
            {   // B prefetch kt+2
                int row = tid >> 1, ch = tid & 1;
                int sw = ch ^ ((row >> 2) & 1);
                cp16(sb + st2 * STAGE + 2 * TILE + row * PITCH + sw * 16,
                     (const char*)(g_w0h + (size_t)row * K0D + (kt + 2) * BK) + ch * 16);
                asm volatile("cp.async.commit_group;" ::: "memory");
            }
            float4 t;
            LOADA0(kt + 2, t);
            int st1 = st + 1; if (st1 >= 3) st1 -= 3;
            *(uint2*)(sm + st1 * STAGE + aoffb)        = split_h4(rA);
            *(uint2*)(sm + st1 * STAGE + TILE + aoffb) = split_l4(rA);
            rA = t;
        } else if (kt + 1 < KT) {
            int st1 = st + 1; if (st1 >= 3) st1 -= 3;
            *(uint2*)(sm + st1 * STAGE + aoffb)        = split_h4(rA);
            *(uint2*)(sm + st1 * STAGE + TILE + aoffb) = split_l4(rA);
        }

        uint32_t s0 = sb + st * STAGE;
        COMPUTE_TILE(s0);
        if (++st == 3) st = 0;
    }
    __syncthreads();
    gemm_epilogue(sm, tid, lane, wm, wn, bx, acc, g_y0, g_sum0, g_sq0);
    #undef LOADA0
}

// ---------------- GEMM1: A = relu(y0*sc0+sh0) fused in-kernel -------------------
__global__ __launch_bounds__(512) void k_gemm1()
{
    constexpr int KDIM = OD, KT = KDIM / BK;   // 16
    __shared__ __align__(16) char sm[SMEMB];
    uint32_t sb = s2u(sm);
    int tid = threadIdx.x, bx = blockIdx.x;
    int wid = tid >> 5, lane = tid & 31;
    int wm = wid & 3, wn = wid >> 2;

    float acc[2][8][4];
    #pragma unroll
    for (int a = 0; a < 2; ++a)
        #pragma unroll
        for (int b = 0; b < 8; ++b)
            #pragma unroll
            for (int c = 0; c < 4; ++c) acc[a][b][c] = 0.f;

    uint32_t sw16 = (uint32_t)((((lane >> 4) ^ (lane >> 2)) & 1) << 4);
    uint32_t a_off = (wm * 32 + (lane & 15)) * PITCH + sw16;
    uint32_t b_off = (wn * 64 + (lane & 15)) * PITCH + sw16;

    int arow = tid >> 2, akq = tid & 3;
    const float* ybase = g_y0 + (size_t)(bx * BM + arow) * OD + akq * 4;
    int aswz = (akq >> 1) ^ ((arow >> 2) & 1);
    uint32_t aoffb = (uint32_t)(arow * PITCH + aswz * 16 + (akq & 1) * 8);

    float4 rA0 = *(const float4*)(ybase + 0 * BK);
    float4 rA  = *(const float4*)(ybase + 1 * BK);
    {
        int c = 0 * BK + akq * 4;
        float4 s4 = *(const float4*)(g_sc0 + c);
        float4 h4 = *(const float4*)(g_sh0 + c);
        rA0.x = fmaxf(fmaf(rA0.x, s4.x, h4.x), 0.f);
        rA0.y = fmaxf(fmaf(rA0.y, s4.y, h4.y), 0.f);
        rA0.z = fmaxf(fmaf(rA0.z, s4.z, h4.z), 0.f);
        rA0.w = fmaxf(fmaf(rA0.w, s4.w, h4.w), 0.f);
        *(uint2*)(sm + aoffb)        = split_h4(rA0);
        *(uint2*)(sm + TILE + aoffb) = split_l4(rA0);
    }
    {
        int row = tid >> 1, ch = tid & 1;
        int sw = ch ^ ((row >> 2) & 1);
        uint32_t d = sb + 2 * TILE + row * PITCH + sw * 16;
        cp16(d, (const char*)(g_w1h + (size_t)row * KDIM + 0 * BK) + ch * 16);
        asm volatile("cp.async.commit_group;" ::: "memory");
        cp16(d + STAGE, (const char*)(g_w1h + (size_t)row * KDIM + 1 * BK) + ch * 16);
        asm volatile("cp.async.commit_group;" ::: "memory");
    }

    int st = 0;
    for (int kt = 0; kt < KT; ++kt) {
        if (kt + 1 < KT) asm volatile("cp.async.wait_group 1;" ::: "memory");
        else             asm volatile("cp.async.wait_group 0;" ::: "memory");
        __syncthreads();

        if (kt + 2 < KT) {
            int st2 = st + 2; if (st2 >= 3) st2 -= 3;
            {
                int row = tid >> 1, ch = tid & 1;
                int sw = ch ^ ((row >> 2) & 1);
                cp16(sb + st2 * STAGE + 2 * TILE + row * PITCH + sw * 16,
                     (const char*)(g_w1h + (size_t)row * KDIM + (kt + 2) * BK) + ch * 16);
                asm volatile("cp.async.commit_group;" ::: "memory");
            }
            float4 t = *(const float4*)(ybase + (kt + 2) * BK);
            int st1 = st + 1; if (st1 >= 3) st1 -= 3;
            int c = (kt + 1) * BK + akq * 4;
            float4 s4 = *(const float4*)(g_sc0 + c);
            float4 h4 = *(const float4*)(g_sh0 + c);
            rA.x = fmaxf(fmaf(rA.x, s4.x, h4.x), 0.f);
            rA.y = fmaxf(fmaf(rA.y, s4.y, h4.y), 0.f);
            rA.z = fmaxf(fmaf(rA.z, s4.z, h4.z), 0.f);
            rA.w = fmaxf(fmaf(rA.w, s4.w, h4.w), 0.f);
            *(uint2*)(sm + st1 * STAGE + aoffb)        = split_h4(rA);
            *(uint2*)(sm + st1 * STAGE + TILE + aoffb) = split_l4(rA);
            rA = t;
        } else if (kt + 1 < KT) {
            int st1 = st + 1; if (st1 >= 3) st1 -= 3;
            int c = (kt + 1) * BK + akq * 4;
            float4 s4 = *(const float4*)(g_sc0 + c);
            float4 h4 = *(const float4*)(g_sh0 + c);
            rA.x = fmaxf(fmaf(rA.x, s4.x, h4.x), 0.f);
            rA.y = fmaxf(fmaf(rA.y, s4.y, h4.y), 0.f);
            rA.z = fmaxf(fmaf(rA.z, s4.z, h4.z), 0.f);
            rA.w = fmaxf(fmaf(rA.w, s4.w, h4.w), 0.f);
            *(uint2*)(sm + st1 * STAGE + aoffb)        = split_h4(rA);
            *(uint2*)(sm + st1 * STAGE + TILE + aoffb) = split_l4(rA);
        }

        uint32_t s0 = sb + st * STAGE;
        COMPUTE_TILE(s0);
        if (++st == 3) st = 0;
    }
    __syncthreads();
    gemm_epilogue(sm, tid, lane, wm, wn, bx, acc, g_y1, g_sum1, g_sq1);
}

// ---------------- finalize BN stats -> per-channel scale / shift ----------------
template <int LAYER>
__global__ void k_fin(const float* __restrict__ g, const float* __restrict__ beta) {
    int o = threadIdx.x;
    float* SUM = (LAYER == 0) ? g_sum0 : g_sum1;
    float* SQ  = (LAYER == 0) ? g_sq0  : g_sq1;
    float* SC  = (LAYER == 0) ? g_sc0  : g_sc1;
    float* SH  = (LAYER == 0) ? g_sh0  : g_sh1;
    float s = 0.f, q = 0.f;
    #pragma unroll
    for (int k = 0; k < NSLOT; ++k) { s += SUM[k * OD + o]; q += SQ[k * OD + o]; }
    const float invM = 1.f / (float)M_TOT;
    float mean = s * invM;
    float var  = q * invM - mean * mean;
    float rstd = rsqrtf(var + BN_EPS);
    float sc = g[o] * rstd;
    SC[o] = sc;
    SH[o] = beta[o] - mean * sc;
}

// ---------------- output: BN1+ReLU fused transpose [m,o] -> [b,o,n] -------------
__global__ void k_out(float* __restrict__ out) {
    __shared__ float tile[32][33];
    int b = blockIdx.z;
    int o0 = blockIdx.y * 32, n0 = blockIdx.x * 32;
    int tx = threadIdx.x, ty = threadIdx.y;
    float sc = g_sc1[o0 + tx], sh = g_sh1[o0 + tx];
    #pragma unroll
    for (int i = 0; i < 32; i += 8) {
        float y = g_y1[((size_t)(b * NPTS + n0 + ty + i)) * OD + o0 + tx];
        tile[ty + i][tx] = fmaxf(fmaf(y, sc, sh), 0.f);
    }
    __syncthreads();
    #pragma unroll
    for (int i = 0; i < 32; i += 8)
        out[((size_t)b * OD + o0 + ty + i) * NPTS + n0 + tx] = tile[tx][ty + i];
}

// ---------------- launch -------------------------------------------------------
extern "C" void kernel_launch(void* const* d_in, const int* in_sizes, int n_in,
                              void* d_out, int out_size) {
    const float* xyz1    = (const float*)d_in[0];
    const float* xyz2    = (const float*)d_in[1];
    const float* points1 = (const float*)d_in[2];
    const float* points2 = (const float*)d_in[3];
    const float* W0      = (const float*)d_in[4];
    const float* g0      = (const float*)d_in[6];
    const float* beta0   = (const float*)d_in[7];
    const float* W1      = (const float*)d_in[8];
    const float* g1      = (const float*)d_in[10];
    const float* beta1   = (const float*)d_in[11];
    float* out = (float*)d_out;

    k_zero<<<(NSLOT * OD + 255) / 256, 256>>>();
    k_wsplit<<<(OD * K0D + 255) / 256, 256>>>(W0, W1);
    k_nn3<<<dim3(NPTS / 256, BATCH), 256>>>(xyz1, xyz2);
    k_tr_p2<<<dim3(SPTS / 32, C2D / 32, BATCH), dim3(32, 8)>>>(points2);
    k_tr_p1<<<dim3(NPTS / 32, C1D / 32, BATCH), dim3(32, 8)>>>(points1);

    k_gemm0<<<M_TOT / BM, 512>>>();
    k_fin<0><<<1, OD>>>(g0, beta0);

    k_gemm1<<<M_TOT / BM, 512>>>();
    k_fin<1><<<1, OD>>>(g1, beta1);

    k_out<<<dim3(NPTS / 32, OD / 32, BATCH), dim3(32, 8)>>>(out);
}

// round 14
// speedup vs baseline: 1.0582x; 1.0582x over previous
#include <cuda_runtime.h>
#include <cuda_fp16.h>
#include <cstdint>

#define BATCH 8
#define NPTS  16384
#define SPTS  2048
#define C1D   128
#define C2D   256
#define K0D   384      // C1+C2
#define OD    256      // both MLP widths
#define M_TOT (BATCH*NPTS)   // 131072
#define BN_EPS 1e-5f
#define NSLOT 8

// GEMM tiling: BM=128, BN=256(=OD), BK=16, 512 threads, 3-stage, 48KB static smem
#define BM 128
#define BN 256
#define BK 16
#define PITCH 32
#define TILE  (128*PITCH)              // 4096 B
#define STAGE (4*TILE)                 // Ah,Al (2 tiles) + B 256 rows (2 tiles) = 16KB
#define SMEMB (3*STAGE)                // 49152 = 48KB

// ---------------- scratch (static device globals; no allocation) ----------------
__device__ __align__(16) float g_p2t[BATCH * SPTS * C2D];
__device__ __align__(16) float g_y0 [(size_t)M_TOT * OD];
__device__ __align__(16) float g_y1 [(size_t)M_TOT * OD];
__device__ __align__(16) __half g_a0h[(size_t)M_TOT * K0D];
__device__ __align__(16) __half g_a0l[(size_t)M_TOT * K0D];
__device__ __align__(16) __half g_w0h[OD * K0D];
__device__ __align__(16) __half g_w1h[OD * OD];
__device__ int   g_idx[M_TOT * 3];
__device__ float g_w  [M_TOT * 3];
__device__ float g_sum0[NSLOT * OD], g_sq0[NSLOT * OD];
__device__ float g_sum1[NSLOT * OD], g_sq1[NSLOT * OD];
__device__ __align__(16) float g_sc0[OD];
__device__ __align__(16) float g_sh0[OD];
__device__ __align__(16) float g_sc1[OD];
__device__ __align__(16) float g_sh1[OD];

// ---------------- asm helpers --------------------------------------------------
__device__ __forceinline__ uint32_t s2u(const void* p) {
    uint32_t a;
    asm("{ .reg .u64 t; cvta.to.shared.u64 t, %1; cvt.u32.u64 %0, t; }" : "=r"(a) : "l"(p));
    return a;
}
__device__ __forceinline__ void cp16(uint32_t s, const void* g) {
    asm volatile("cp.async.cg.shared.global [%0], [%1], 16;" :: "r"(s), "l"(g));
}
#define LDX4(r, addr)                                                          \
    asm volatile("ldmatrix.sync.aligned.m8n8.x4.shared.b16 {%0,%1,%2,%3}, [%4];" \
        : "=r"((r)[0]), "=r"((r)[1]), "=r"((r)[2]), "=r"((r)[3]) : "r"(addr))
#define MMA(d, a, b0, b1)                                                      \
    asm volatile("mma.sync.aligned.m16n8k16.row.col.f32.f16.f16.f32 "          \
        "{%0,%1,%2,%3}, {%4,%5,%6,%7}, {%8,%9}, {%0,%1,%2,%3};"                \
        : "+f"((d)[0]), "+f"((d)[1]), "+f"((d)[2]), "+f"((d)[3])               \
        : "r"((a)[0]), "r"((a)[1]), "r"((a)[2]), "r"((a)[3]), "r"(b0), "r"(b1))

__device__ __forceinline__ uint2 split_h4(float4 v) {
    __half2 a, b;
    a.x = __float2half_rn(v.x); a.y = __float2half_rn(v.y);
    b.x = __float2half_rn(v.z); b.y = __float2half_rn(v.w);
    uint2 r; r.x = *(uint32_t*)&a; r.y = *(uint32_t*)&b;
    return r;
}
__device__ __forceinline__ uint2 split_l4(float4 v) {
    __half hx = __float2half_rn(v.x), hy = __float2half_rn(v.y);
    __half hz = __float2half_rn(v.z), hw = __float2half_rn(v.w);
    __half2 a, b;
    a.x = __float2half_rn(v.x - __half2float(hx));
    a.y = __float2half_rn(v.y - __half2float(hy));
    b.x = __float2half_rn(v.z - __half2float(hz));
    b.y = __float2half_rn(v.w - __half2float(hw));
    uint2 r; r.x = *(uint32_t*)&a; r.y = *(uint32_t*)&b;
    return r;
}

// ---------------- kernel: zero stats + round W to fp16 (merged) -----------------
__global__ void k_init(const float* __restrict__ W0, const float* __restrict__ W1) {
    int t = blockIdx.x * blockDim.x + threadIdx.x;
    if (t < NSLOT * OD) { g_sum0[t] = 0.f; g_sq0[t] = 0.f; g_sum1[t] = 0.f; g_sq1[t] = 0.f; }
    if (t < OD * K0D) g_w0h[t] = __float2half_rn(W0[t]);
    if (t < OD * OD)  g_w1h[t] = __float2half_rn(W1[t]);
}

// ---------------- kernel: 3-NN + inverse-distance weights ----------------------
// Per-candidate distance math bit-identical to reference; 4-wide guard.
__device__ __forceinline__ void nn_ins(float d, int s,
    float& d0, float& d1, float& d2, int& i0, int& i1, int& i2) {
    if (d < d2) {
        if (d < d1) {
            d2 = d1; i2 = i1;
            if (d < d0) { d1 = d0; i1 = i0; d0 = d; i0 = s; }
            else        { d1 = d;  i1 = s; }
        } else { d2 = d; i2 = s; }
    }
}
__global__ void k_nn3(const float* __restrict__ xyz1, const float* __restrict__ xyz2) {
    __shared__ float4 sp[SPTS];
    int b = blockIdx.y;
    const float* x2 = xyz2 + (size_t)b * SPTS * 3;
    for (int i = threadIdx.x; i < SPTS * 3; i += blockDim.x) {
        int s = i / 3, d = i - 3 * s;
        ((float*)&sp[s])[d] = x2[i];
    }
    __syncthreads();

    int n = blockIdx.x * blockDim.x + threadIdx.x;
    const float* p = xyz1 + ((size_t)b * NPTS + n) * 3;
    float px = p[0], py = p[1], pz = p[2];

    float d0 = 1e30f, d1 = 1e30f, d2 = 1e30f;
    int   i0 = 0,     i1 = 0,     i2 = 0;
    #pragma unroll 1
    for (int s = 0; s < SPTS; s += 4) {
        float4 q0 = sp[s], q1 = sp[s + 1], q2 = sp[s + 2], q3 = sp[s + 3];
        float dx = px - q0.x, dy = py - q0.y, dz = pz - q0.z;
        float da = fmaf(dx, dx, fmaf(dy, dy, dz * dz));
        dx = px - q1.x; dy = py - q1.y; dz = pz - q1.z;
        float db = fmaf(dx, dx, fmaf(dy, dy, dz * dz));
        dx = px - q2.x; dy = py - q2.y; dz = pz - q2.z;
        float dc = fmaf(dx, dx, fmaf(dy, dy, dz * dz));
        dx = px - q3.x; dy = py - q3.y; dz = pz - q3.z;
        float dd = fmaf(dx, dx, fmaf(dy, dy, dz * dz));
        float mn = fminf(fminf(da, db), fminf(dc, dd));
        if (mn < d2) {
            nn_ins(da, s,     d0, d1, d2, i0, i1, i2);
            nn_ins(db, s + 1, d0, d1, d2, i0, i1, i2);
            nn_ins(dc, s + 2, d0, d1, d2, i0, i1, i2);
            nn_ins(dd, s + 3, d0, d1, d2, i0, i1, i2);
        }
    }
    d0 = fmaxf(d0, 1e-10f); d1 = fmaxf(d1, 1e-10f); d2 = fmaxf(d2, 1e-10f);
    float w0 = 1.f / d0, w1 = 1.f / d1, w2 = 1.f / d2;
    float inv = 1.f / (w0 + w1 + w2);
    int base = ((b * NPTS) + n) * 3;
    g_idx[base] = i0; g_idx[base + 1] = i1; g_idx[base + 2] = i2;
    g_w[base] = w0 * inv; g_w[base + 1] = w1 * inv; g_w[base + 2] = w2 * inv;
}

// ---------------- transpose points2 [b,c,s] -> [b,s,c] -------------------------
__global__ void k_tr_p2(const float* __restrict__ p2) {
    __shared__ float tile[32][33];
    int b = blockIdx.z;
    int c0 = blockIdx.y * 32, s0 = blockIdx.x * 32;
    int tx = threadIdx.x, ty = threadIdx.y;
    #pragma unroll
    for (int i = 0; i < 32; i += 8)
        tile[ty + i][tx] = p2[((size_t)(b * C2D + c0 + ty + i)) * SPTS + s0 + tx];
    __syncthreads();
    #pragma unroll
    for (int i = 0; i < 32; i += 8)
        g_p2t[((size_t)(b * SPTS + s0 + ty + i)) * C2D + c0 + tx] = tile[tx][ty + i];
}

// ---------------- interp -> a0 cols [0,256) as split fp16 ----------------------
__global__ void k_interp() {
    int gwarp = (blockIdx.x * blockDim.x + threadIdx.x) >> 5;
    int lane  = threadIdx.x & 31;
    int b = gwarp >> 14;
    int base = gwarp * 3;
    int i0 = g_idx[base], i1 = g_idx[base + 1], i2 = g_idx[base + 2];
    float w0 = g_w[base], w1 = g_w[base + 1], w2 = g_w[base + 2];
    const float4* r0 = (const float4*)(g_p2t + ((size_t)b * SPTS + i0) * C2D);
    const float4* r1 = (const float4*)(g_p2t + ((size_t)b * SPTS + i1) * C2D);
    const float4* r2 = (const float4*)(g_p2t + ((size_t)b * SPTS + i2) * C2D);
    uint2* hrow = (uint2*)(g_a0h + (size_t)gwarp * K0D);
    uint2* lrow = (uint2*)(g_a0l + (size_t)gwarp * K0D);
    #pragma unroll
    for (int c = lane; c < C2D / 4; c += 32) {
        float4 a = r0[c], bb = r1[c], cc = r2[c], o;
        o.x = w0 * a.x + w1 * bb.x + w2 * cc.x;
        o.y = w0 * a.y + w1 * bb.y + w2 * cc.y;
        o.z = w0 * a.z + w1 * bb.z + w2 * cc.z;
        o.w = w0 * a.w + w1 * bb.w + w2 * cc.w;
        hrow[c] = split_h4(o);
        lrow[c] = split_l4(o);
    }
}

// ---------------- points1 [b,c,n] -> a0 cols [256,384) split fp16 ---------------
__global__ void k_tr_p1(const float* __restrict__ p1) {
    __shared__ float tile[32][33];
    int b = blockIdx.z;
    int c0 = blockIdx.y * 32, n0 = blockIdx.x * 32;
    int tx = threadIdx.x, ty = threadIdx.y;
    #pragma unroll
    for (int i = 0; i < 32; i += 8)
        tile[ty + i][tx] = p1[((size_t)(b * C1D + c0 + ty + i)) * NPTS + n0 + tx];
    __syncthreads();
    #pragma unroll
    for (int i = 0; i < 32; i += 8) {
        float v = tile[tx][ty + i];
        __half h = __float2half_rn(v);
        size_t off = ((size_t)(b * NPTS + n0 + ty + i)) * K0D + C2D + c0 + tx;
        g_a0h[off] = h;
        g_a0l[off] = __float2half_rn(v - __half2float(h));
    }
}

// ---------------- GEMM0: fp16 2-pass, A/B via cp.async -------------------------
__device__ __forceinline__ void load_stage0(
    uint32_t s0, int bx, int tid, int kt)
{
    {   // A halves: tid<256 -> Ah, tid>=256 -> Al (256 cp16 each)
        int hsel = tid >> 8;
        int q = tid & 255;
        int row = q >> 1, ch = q & 1;
        int sw = ch ^ ((row >> 2) & 1);
        uint32_t d = s0 + hsel * TILE + row * PITCH + sw * 16;
        const __half* src = hsel ? g_a0l : g_a0h;
        cp16(d, (const char*)(src + (size_t)(bx * BM + row) * K0D + kt * BK) + ch * 16);
    }
    {   // B: 256 rows x 2 chunks = 512 cp16
        int row = tid >> 1, ch = tid & 1;
        int sw = ch ^ ((row >> 2) & 1);
        uint32_t d = s0 + 2 * TILE + row * PITCH + sw * 16;
        cp16(d, (const char*)(g_w0h + (size_t)row * K0D + kt * BK) + ch * 16);
    }
    asm volatile("cp.async.commit_group;" ::: "memory");
}

// shared epilogue: C store + stats (BN=256 full width)
__device__ __forceinline__ void gemm_epilogue(
    char* sm, int tid, int lane, int wm, int wn, int bx,
    float (*acc)[8][4], float* C, float* GS, float* GQ)
{
    float* ssum = (float*)sm;
    float* ssq  = ((float*)sm) + BN;
    if (tid < BN) { ssum[tid] = 0.f; ssq[tid] = 0.f; }
    __syncthreads();

    int rbase = bx * BM + wm * 32 + (lane >> 2);
    int cbase = wn * 64 + (lane & 3) * 2;
    #pragma unroll
    for (int mf = 0; mf < 2; ++mf)
        #pragma unroll
        for (int g = 0; g < 8; ++g) {
            *(float2*)(C + (size_t)(rbase + mf * 16) * OD + cbase + g * 8) =
                make_float2(acc[mf][g][0], acc[mf][g][1]);
            *(float2*)(C + (size_t)(rbase + mf * 16 + 8) * OD + cbase + g * 8) =
                make_float2(acc[mf][g][2], acc[mf][g][3]);
        }

    #pragma unroll
    for (int g = 0; g < 8; ++g)
        #pragma unroll
        for (int e = 0; e < 2; ++e) {
            float v0 = acc[0][g][e], v1 = acc[0][g][e + 2];
            float v2 = acc[1][g][e], v3 = acc[1][g][e + 2];
            float s = v0 + v1 + v2 + v3;
            float q = fmaf(v0, v0, fmaf(v1, v1, fmaf(v2, v2, v3 * v3)));
            #pragma unroll
            for (int m = 4; m < 32; m <<= 1) {
                s += __shfl_xor_sync(0xffffffffu, s, m);
                q += __shfl_xor_sync(0xffffffffu, q, m);
            }
            if ((lane >> 2) == 0) {
                int col = cbase + g * 8 + e;
                atomicAdd(&ssum[col], s);
                atomicAdd(&ssq[col], q);
            }
        }
    __syncthreads();
    if (tid < BN) {
        int slot = (bx & (NSLOT - 1)) * OD + tid;
        atomicAdd(&GS[slot], ssum[tid]);
        atomicAdd(&GQ[slot], ssq[tid]);
    }
}

#define COMPUTE_TILE(s0)                                                       \
    do {                                                                       \
        uint32_t ah[2][4], al[2][4];                                           \
        _Pragma("unroll")                                                      \
        for (int mf = 0; mf < 2; ++mf) {                                       \
            uint32_t aa = (s0) + a_off + mf * 16 * PITCH;                      \
            LDX4(ah[mf], aa);                                                  \
            LDX4(al[mf], aa + TILE);                                           \
        }                                                                      \
        _Pragma("unroll")                                                      \
        for (int g = 0; g < 4; ++g) {                                          \
            uint32_t ba = (s0) + 2 * TILE + b_off + g * 16 * PITCH;            \
            uint32_t bb[4];                                                    \
            LDX4(bb, ba);                                                      \
            _Pragma("unroll")                                                  \
            for (int mf = 0; mf < 2; ++mf) {                                   \
                MMA(acc[mf][2 * g],     ah[mf], bb[0], bb[2]);                 \
                MMA(acc[mf][2 * g + 1], ah[mf], bb[1], bb[3]);                 \
                MMA(acc[mf][2 * g],     al[mf], bb[0], bb[2]);                 \
                MMA(acc[mf][2 * g + 1], al[mf], bb[1], bb[3]);                 \
            }                                                                  \
        }                                                                      \
    } while (0)

__global__ __launch_bounds__(512) void k_gemm0()
{
    constexpr int KT = K0D / BK;   // 24
    __shared__ __align__(16) char sm[SMEMB];
    uint32_t sb = s2u(sm);
    int tid = threadIdx.x, bx = blockIdx.x;
    int wid = tid >> 5, lane = tid & 31;
    int wm = wid & 3, wn = wid >> 2;

    float acc[2][8][4];
    #pragma unroll
    for (int a = 0; a < 2; ++a)
        #pragma unroll
        for (int b = 0; b < 8; ++b)
            #pragma unroll
            for (int c = 0; c < 4; ++c) acc[a][b][c] = 0.f;

    uint32_t sw16 = (uint32_t)((((lane >> 4) ^ (lane >> 2)) & 1) << 4);
    uint32_t a_off = (wm * 32 + (lane & 15)) * PITCH + sw16;
    uint32_t b_off = (wn * 64 + (lane & 15)) * PITCH + sw16;

    load_stage0(sb, bx, tid, 0);
    load_stage0(sb + STAGE, bx, tid, 1);

    int st = 0;
    for (int kt = 0; kt < KT; ++kt) {
        if (kt + 1 < KT) asm volatile("cp.async.wait_group 1;" ::: "memory");
        else             asm volatile("cp.async.wait_group 0;" ::: "memory");
        __syncthreads();
        if (kt + 2 < KT) {
            int st2 = st + 2; if (st2 >= 3) st2 -= 3;
            load_stage0(sb + st2 * STAGE, bx, tid, kt + 2);
        }
        uint32_t s0 = sb + st * STAGE;
        COMPUTE_TILE(s0);
        if (++st == 3) st = 0;
    }
    __syncthreads();
    gemm_epilogue(sm, tid, lane, wm, wn, bx, acc, g_y0, g_sum0, g_sq0);
}

// ---------------- GEMM1: A = relu(y0*sc0+sh0) fused in-kernel -------------------
__global__ __launch_bounds__(512) void k_gemm1()
{
    constexpr int KDIM = OD, KT = KDIM / BK;   // 16
    __shared__ __align__(16) char sm[SMEMB];
    uint32_t sb = s2u(sm);
    int tid = threadIdx.x, bx = blockIdx.x;
    int wid = tid >> 5, lane = tid & 31;
    int wm = wid & 3, wn = wid >> 2;

    float acc[2][8][4];
    #pragma unroll
    for (int a = 0; a < 2; ++a)
        #pragma unroll
        for (int b = 0; b < 8; ++b)
            #pragma unroll
            for (int c = 0; c < 4; ++c) acc[a][b][c] = 0.f;

    uint32_t sw16 = (uint32_t)((((lane >> 4) ^ (lane >> 2)) & 1) << 4);
    uint32_t a_off = (wm * 32 + (lane & 15)) * PITCH + sw16;
    uint32_t b_off = (wn * 64 + (lane & 15)) * PITCH + sw16;

    int arow = tid >> 2, akq = tid & 3;
    const float* ybase = g_y0 + (size_t)(bx * BM + arow) * OD + akq * 4;
    int aswz = (akq >> 1) ^ ((arow >> 2) & 1);
    uint32_t aoffb = (uint32_t)(arow * PITCH + aswz * 16 + (akq & 1) * 8);

    float4 rA0 = *(const float4*)(ybase + 0 * BK);
    float4 rA  = *(const float4*)(ybase + 1 * BK);
    {
        int c = 0 * BK + akq * 4;
        float4 s4 = *(const float4*)(g_sc0 + c);
        float4 h4 = *(const float4*)(g_sh0 + c);
        rA0.x = fmaxf(fmaf(rA0.x, s4.x, h4.x), 0.f);
        rA0.y = fmaxf(fmaf(rA0.y, s4.y, h4.y), 0.f);
        rA0.z = fmaxf(fmaf(rA0.z, s4.z, h4.z), 0.f);
        rA0.w = fmaxf(fmaf(rA0.w, s4.w, h4.w), 0.f);
        *(uint2*)(sm + aoffb)        = split_h4(rA0);
        *(uint2*)(sm + TILE + aoffb) = split_l4(rA0);
    }
    {
        int row = tid >> 1, ch = tid & 1;
        int sw = ch ^ ((row >> 2) & 1);
        uint32_t d = sb + 2 * TILE + row * PITCH + sw * 16;
        cp16(d, (const char*)(g_w1h + (size_t)row * KDIM + 0 * BK) + ch * 16);
        asm volatile("cp.async.commit_group;" ::: "memory");
        cp16(d + STAGE, (const char*)(g_w1h + (size_t)row * KDIM + 1 * BK) + ch * 16);
        asm volatile("cp.async.commit_group;" ::: "memory");
    }

    int st = 0;
    for (int kt = 0; kt < KT; ++kt) {
        if (kt + 1 < KT) asm volatile("cp.async.wait_group 1;" ::: "memory");
        else             asm volatile("cp.async.wait_group 0;" ::: "memory");
        __syncthreads();

        if (kt + 2 < KT) {
            int st2 = st + 2; if (st2 >= 3) st2 -= 3;
            {
                int row = tid >> 1, ch = tid & 1;
                int sw = ch ^ ((row >> 2) & 1);
                cp16(sb + st2 * STAGE + 2 * TILE + row * PITCH + sw * 16,
                     (const char*)(g_w1h + (size_t)row * KDIM + (kt + 2) * BK) + ch * 16);
                asm volatile("cp.async.commit_group;" ::: "memory");
            }
            float4 t = *(const float4*)(ybase + (kt + 2) * BK);
            int st1 = st + 1; if (st1 >= 3) st1 -= 3;
            int c = (kt + 1) * BK + akq * 4;
            float4 s4 = *(const float4*)(g_sc0 + c);
            float4 h4 = *(const float4*)(g_sh0 + c);
            rA.x = fmaxf(fmaf(rA.x, s4.x, h4.x), 0.f);
            rA.y = fmaxf(fmaf(rA.y, s4.y, h4.y), 0.f);
            rA.z = fmaxf(fmaf(rA.z, s4.z, h4.z), 0.f);
            rA.w = fmaxf(fmaf(rA.w, s4.w, h4.w), 0.f);
            *(uint2*)(sm + st1 * STAGE + aoffb)        = split_h4(rA);
            *(uint2*)(sm + st1 * STAGE + TILE + aoffb) = split_l4(rA);
            rA = t;
        } else if (kt + 1 < KT) {
            int st1 = st + 1; if (st1 >= 3) st1 -= 3;
            int c = (kt + 1) * BK + akq * 4;
            float4 s4 = *(const float4*)(g_sc0 + c);
            float4 h4 = *(const float4*)(g_sh0 + c);
            rA.x = fmaxf(fmaf(rA.x, s4.x, h4.x), 0.f);
            rA.y = fmaxf(fmaf(rA.y, s4.y, h4.y), 0.f);
            rA.z = fmaxf(fmaf(rA.z, s4.z, h4.z), 0.f);
            rA.w = fmaxf(fmaf(rA.w, s4.w, h4.w), 0.f);
            *(uint2*)(sm + st1 * STAGE + aoffb)        = split_h4(rA);
            *(uint2*)(sm + st1 * STAGE + TILE + aoffb) = split_l4(rA);
        }

        uint32_t s0 = sb + st * STAGE;
        COMPUTE_TILE(s0);
        if (++st == 3) st = 0;
    }
    __syncthreads();
    gemm_epilogue(sm, tid, lane, wm, wn, bx, acc, g_y1, g_sum1, g_sq1);
}

// ---------------- finalize BN stats -> per-channel scale / shift ----------------
template <int LAYER>
__global__ void k_fin(const float* __restrict__ g, const float* __restrict__ beta) {
    int o = threadIdx.x;
    float* SUM = (LAYER == 0) ? g_sum0 : g_sum1;
    float* SQ  = (LAYER == 0) ? g_sq0  : g_sq1;
    float* SC  = (LAYER == 0) ? g_sc0  : g_sc1;
    float* SH  = (LAYER == 0) ? g_sh0  : g_sh1;
    float s = 0.f, q = 0.f;
    #pragma unroll
    for (int k = 0; k < NSLOT; ++k) { s += SUM[k * OD + o]; q += SQ[k * OD + o]; }
    const float invM = 1.f / (float)M_TOT;
    float mean = s * invM;
    float var  = q * invM - mean * mean;
    float rstd = rsqrtf(var + BN_EPS);
    float sc = g[o] * rstd;
    SC[o] = sc;
    SH[o] = beta[o] - mean * sc;
}

// ---------------- output: BN1+ReLU fused transpose [m,o] -> [b,o,n] -------------
__global__ void k_out(float* __restrict__ out) {
    __shared__ float tile[32][33];
    int b = blockIdx.z;
    int o0 = blockIdx.y * 32, n0 = blockIdx.x * 32;
    int tx = threadIdx.x, ty = threadIdx.y;
    float sc = g_sc1[o0 + tx], sh = g_sh1[o0 + tx];
    #pragma unroll
    for (int i = 0; i < 32; i += 8) {
        float y = g_y1[((size_t)(b * NPTS + n0 + ty + i)) * OD + o0 + tx];
        tile[ty + i][tx] = fmaxf(fmaf(y, sc, sh), 0.f);
    }
    __syncthreads();
    #pragma unroll
    for (int i = 0; i < 32; i += 8)
        out[((size_t)b * OD + o0 + ty + i) * NPTS + n0 + tx] = tile[tx][ty + i];
}

// ---------------- launch -------------------------------------------------------
extern "C" void kernel_launch(void* const* d_in, const int* in_sizes, int n_in,
                              void* d_out, int out_size) {
    const float* xyz1    = (const float*)d_in[0];
    const float* xyz2    = (const float*)d_in[1];
    const float* points1 = (const float*)d_in[2];
    const float* points2 = (const float*)d_in[3];
    const float* W0      = (const float*)d_in[4];
    const float* g0      = (const float*)d_in[6];
    const float* beta0   = (const float*)d_in[7];
    const float* W1      = (const float*)d_in[8];
    const float* g1      = (const float*)d_in[10];
    const float* beta1   = (const float*)d_in[11];
    float* out = (float*)d_out;

    k_init<<<(OD * K0D + 255) / 256, 256>>>(W0, W1);
    k_nn3<<<dim3(NPTS / 256, BATCH), 256>>>(xyz1, xyz2);
    k_tr_p2<<<dim3(SPTS / 32, C2D / 32, BATCH), dim3(32, 8)>>>(points2);
    k_interp<<<M_TOT / 8, 256>>>();
    k_tr_p1<<<dim3(NPTS / 32, C1D / 32, BATCH), dim3(32, 8)>>>(points1);

    k_gemm0<<<M_TOT / BM, 512>>>();
    k_fin<0><<<1, OD>>>(g0, beta0);

    k_gemm1<<<M_TOT / BM, 512>>>();
    k_fin<1><<<1, OD>>>(g1, beta1);

    k_out<<<dim3(NPTS / 32, OD / 32, BATCH), dim3(32, 8)>>>(out);
}

// round 15
// speedup vs baseline: 1.0620x; 1.0036x over previous
#include <cuda_runtime.h>
#include <cuda_fp16.h>
#include <cstdint>

#define BATCH 8
#define NPTS  16384
#define SPTS  2048
#define C1D   128
#define C2D   256
#define K0D   384      // C1+C2
#define OD    256      // both MLP widths
#define M_TOT (BATCH*NPTS)   // 131072
#define BN_EPS 1e-5f
#define NSLOT 8

// GEMM tiling: BM=128, BN=256(=OD), BK=16, 512 threads, 3-stage, 48KB static smem
#define BM 128
#define BN 256
#define BK 16
#define PITCH 32
#define TILE  (128*PITCH)              // 4096 B
#define STAGE (4*TILE)                 // Ah,Al (2 tiles) + B 256 rows (2 tiles) = 16KB
#define SMEMB (3*STAGE)                // 49152 = 48KB

// fat pre-kernel role ranges
#define NN3_BLKS  (NPTS/256*BATCH)                 // 512
#define TP2_BLKS  ((SPTS/32)*(C2D/32)*BATCH)       // 4096
#define TP1_BLKS  ((NPTS/32)*(C1D/32)*BATCH)       // 16384
#define PRE_BLKS  (NN3_BLKS+TP2_BLKS+TP1_BLKS)

// ---------------- scratch (static device globals; no allocation) ----------------
__device__ __align__(16) float g_p2t[BATCH * SPTS * C2D];
__device__ __align__(16) float g_y0 [(size_t)M_TOT * OD];
__device__ __align__(16) float g_y1 [(size_t)M_TOT * OD];
__device__ __align__(16) __half g_a0h[(size_t)M_TOT * K0D];
__device__ __align__(16) __half g_a0l[(size_t)M_TOT * K0D];
__device__ __align__(16) __half g_w0h[OD * K0D];
__device__ __align__(16) __half g_w1h[OD * OD];
__device__ int   g_idx[M_TOT * 3];
__device__ float g_w  [M_TOT * 3];
__device__ float g_sum0[NSLOT * OD], g_sq0[NSLOT * OD];
__device__ float g_sum1[NSLOT * OD], g_sq1[NSLOT * OD];
__device__ __align__(16) float g_sc0[OD];
__device__ __align__(16) float g_sh0[OD];

// ---------------- asm helpers --------------------------------------------------
__device__ __forceinline__ uint32_t s2u(const void* p) {
    uint32_t a;
    asm("{ .reg .u64 t; cvta.to.shared.u64 t, %1; cvt.u32.u64 %0, t; }" : "=r"(a) : "l"(p));
    return a;
}
__device__ __forceinline__ void cp16(uint32_t s, const void* g) {
    asm volatile("cp.async.cg.shared.global [%0], [%1], 16;" :: "r"(s), "l"(g));
}
#define LDX4(r, addr)                                                          \
    asm volatile("ldmatrix.sync.aligned.m8n8.x4.shared.b16 {%0,%1,%2,%3}, [%4];" \
        : "=r"((r)[0]), "=r"((r)[1]), "=r"((r)[2]), "=r"((r)[3]) : "r"(addr))
#define MMA(d, a, b0, b1)                                                      \
    asm volatile("mma.sync.aligned.m16n8k16.row.col.f32.f16.f16.f32 "          \
        "{%0,%1,%2,%3}, {%4,%5,%6,%7}, {%8,%9}, {%0,%1,%2,%3};"                \
        : "+f"((d)[0]), "+f"((d)[1]), "+f"((d)[2]), "+f"((d)[3])               \
        : "r"((a)[0]), "r"((a)[1]), "r"((a)[2]), "r"((a)[3]), "r"(b0), "r"(b1))

__device__ __forceinline__ uint2 split_h4(float4 v) {
    __half2 a, b;
    a.x = __float2half_rn(v.x); a.y = __float2half_rn(v.y);
    b.x = __float2half_rn(v.z); b.y = __float2half_rn(v.w);
    uint2 r; r.x = *(uint32_t*)&a; r.y = *(uint32_t*)&b;
    return r;
}
__device__ __forceinline__ uint2 split_l4(float4 v) {
    __half hx = __float2half_rn(v.x), hy = __float2half_rn(v.y);
    __half hz = __float2half_rn(v.z), hw = __float2half_rn(v.w);
    __half2 a, b;
    a.x = __float2half_rn(v.x - __half2float(hx));
    a.y = __float2half_rn(v.y - __half2float(hy));
    b.x = __float2half_rn(v.z - __half2float(hz));
    b.y = __float2half_rn(v.w - __half2float(hw));
    uint2 r; r.x = *(uint32_t*)&a; r.y = *(uint32_t*)&b;
    return r;
}

// ---------------- kernel: zero stats + round W to fp16 (merged) -----------------
__global__ void k_init(const float* __restrict__ W0, const float* __restrict__ W1) {
    int t = blockIdx.x * blockDim.x + threadIdx.x;
    if (t < NSLOT * OD) { g_sum0[t] = 0.f; g_sq0[t] = 0.f; g_sum1[t] = 0.f; g_sq1[t] = 0.f; }
    if (t < OD * K0D) g_w0h[t] = __float2half_rn(W0[t]);
    if (t < OD * OD)  g_w1h[t] = __float2half_rn(W1[t]);
}

// ---------------- fat pre-kernel: nn3 | tr_p2 | tr_p1 ---------------------------
__device__ __forceinline__ void nn_ins(float d, int s,
    float& d0, float& d1, float& d2, int& i0, int& i1, int& i2) {
    if (d < d2) {
        if (d < d1) {
            d2 = d1; i2 = i1;
            if (d < d0) { d1 = d0; i1 = i0; d0 = d; i0 = s; }
            else        { d1 = d;  i1 = s; }
        } else { d2 = d; i2 = s; }
    }
}

__global__ __launch_bounds__(256) void k_pre(
    const float* __restrict__ xyz1, const float* __restrict__ xyz2,
    const float* __restrict__ p1,   const float* __restrict__ p2)
{
    __shared__ __align__(16) char smraw[SPTS * 16];   // 32KB: sp[2048] or tile[32][33]
    int bid = blockIdx.x, tid = threadIdx.x;

    if (bid < NN3_BLKS) {
        // ---- role: 3-NN (exact reference distances, 4-wide guard) ----
        float4* sp = (float4*)smraw;
        int b = bid >> 6;                       // NPTS/256 = 64 blocks per batch
        const float* x2 = xyz2 + (size_t)b * SPTS * 3;
        for (int i = tid; i < SPTS * 3; i += 256) {
            int s = i / 3, d = i - 3 * s;
            ((float*)&sp[s])[d] = x2[i];
        }
        __syncthreads();

        int n = (bid & 63) * 256 + tid;
        const float* p = xyz1 + ((size_t)b * NPTS + n) * 3;
        float px = p[0], py = p[1], pz = p[2];

        float d0 = 1e30f, d1 = 1e30f, d2 = 1e30f;
        int   i0 = 0,     i1 = 0,     i2 = 0;
        #pragma unroll 1
        for (int s = 0; s < SPTS; s += 4) {
            float4 q0 = sp[s], q1 = sp[s + 1], q2 = sp[s + 2], q3 = sp[s + 3];
            float dx = px - q0.x, dy = py - q0.y, dz = pz - q0.z;
            float da = fmaf(dx, dx, fmaf(dy, dy, dz * dz));
            dx = px - q1.x; dy = py - q1.y; dz = pz - q1.z;
            float db = fmaf(dx, dx, fmaf(dy, dy, dz * dz));
            dx = px - q2.x; dy = py - q2.y; dz = pz - q2.z;
            float dc = fmaf(dx, dx, fmaf(dy, dy, dz * dz));
            dx = px - q3.x; dy = py - q3.y; dz = pz - q3.z;
            float dd = fmaf(dx, dx, fmaf(dy, dy, dz * dz));
            float mn = fminf(fminf(da, db), fminf(dc, dd));
            if (mn < d2) {
                nn_ins(da, s,     d0, d1, d2, i0, i1, i2);
                nn_ins(db, s + 1, d0, d1, d2, i0, i1, i2);
                nn_ins(dc, s + 2, d0, d1, d2, i0, i1, i2);
                nn_ins(dd, s + 3, d0, d1, d2, i0, i1, i2);
            }
        }
        d0 = fmaxf(d0, 1e-10f); d1 = fmaxf(d1, 1e-10f); d2 = fmaxf(d2, 1e-10f);
        float w0 = 1.f / d0, w1 = 1.f / d1, w2 = 1.f / d2;
        float inv = 1.f / (w0 + w1 + w2);
        int base = ((b * NPTS) + n) * 3;
        g_idx[base] = i0; g_idx[base + 1] = i1; g_idx[base + 2] = i2;
        g_w[base] = w0 * inv; g_w[base + 1] = w1 * inv; g_w[base + 2] = w2 * inv;
    } else if (bid < NN3_BLKS + TP2_BLKS) {
        // ---- role: transpose points2 [b,c,s] -> [b,s,c] ----
        float (*tile)[33] = (float(*)[33])smraw;
        int q = bid - NN3_BLKS;
        int s0 = (q & 63) * 32;                 // 64 s-blocks
        int c0 = ((q >> 6) & 7) * 32;           // 8 c-blocks
        int b  = q >> 9;
        int tx = tid & 31, ty = tid >> 5;
        #pragma unroll
        for (int i = 0; i < 32; i += 8)
            tile[ty + i][tx] = p2[((size_t)(b * C2D + c0 + ty + i)) * SPTS + s0 + tx];
        __syncthreads();
        #pragma unroll
        for (int i = 0; i < 32; i += 8)
            g_p2t[((size_t)(b * SPTS + s0 + ty + i)) * C2D + c0 + tx] = tile[tx][ty + i];
    } else {
        // ---- role: points1 [b,c,n] -> a0 cols [256,384) split fp16 ----
        float (*tile)[33] = (float(*)[33])smraw;
        int q = bid - NN3_BLKS - TP2_BLKS;
        int n0 = (q & 511) * 32;                // 512 n-blocks
        int c0 = ((q >> 9) & 3) * 32;           // 4 c-blocks
        int b  = q >> 11;
        int tx = tid & 31, ty = tid >> 5;
        #pragma unroll
        for (int i = 0; i < 32; i += 8)
            tile[ty + i][tx] = p1[((size_t)(b * C1D + c0 + ty + i)) * NPTS + n0 + tx];
        __syncthreads();
        #pragma unroll
        for (int i = 0; i < 32; i += 8) {
            float v = tile[tx][ty + i];
            __half h = __float2half_rn(v);
            size_t off = ((size_t)(b * NPTS + n0 + ty + i)) * K0D + C2D + c0 + tx;
            g_a0h[off] = h;
            g_a0l[off] = __float2half_rn(v - __half2float(h));
        }
    }
}

// ---------------- interp -> a0 cols [0,256) as split fp16 ----------------------
__global__ void k_interp() {
    int gwarp = (blockIdx.x * blockDim.x + threadIdx.x) >> 5;
    int lane  = threadIdx.x & 31;
    int b = gwarp >> 14;
    int base = gwarp * 3;
    int i0 = g_idx[base], i1 = g_idx[base + 1], i2 = g_idx[base + 2];
    float w0 = g_w[base], w1 = g_w[base + 1], w2 = g_w[base + 2];
    const float4* r0 = (const float4*)(g_p2t + ((size_t)b * SPTS + i0) * C2D);
    const float4* r1 = (const float4*)(g_p2t + ((size_t)b * SPTS + i1) * C2D);
    const float4* r2 = (const float4*)(g_p2t + ((size_t)b * SPTS + i2) * C2D);
    uint2* hrow = (uint2*)(g_a0h + (size_t)gwarp * K0D);
    uint2* lrow = (uint2*)(g_a0l + (size_t)gwarp * K0D);
    #pragma unroll
    for (int c = lane; c < C2D / 4; c += 32) {
        float4 a = r0[c], bb = r1[c], cc = r2[c], o;
        o.x = w0 * a.x + w1 * bb.x + w2 * cc.x;
        o.y = w0 * a.y + w1 * bb.y + w2 * cc.y;
        o.z = w0 * a.z + w1 * bb.z + w2 * cc.z;
        o.w = w0 * a.w + w1 * bb.w + w2 * cc.w;
        hrow[c] = split_h4(o);
        lrow[c] = split_l4(o);
    }
}

// ---------------- GEMM pieces ---------------------------------------------------
__device__ __forceinline__ void load_stage0(
    uint32_t s0, int bx, int tid, int kt)
{
    {
        int hsel = tid >> 8;
        int q = tid & 255;
        int row = q >> 1, ch = q & 1;
        int sw = ch ^ ((row >> 2) & 1);
        uint32_t d = s0 + hsel * TILE + row * PITCH + sw * 16;
        const __half* src = hsel ? g_a0l : g_a0h;
        cp16(d, (const char*)(src + (size_t)(bx * BM + row) * K0D + kt * BK) + ch * 16);
    }
    {
        int row = tid >> 1, ch = tid & 1;
        int sw = ch ^ ((row >> 2) & 1);
        uint32_t d = s0 + 2 * TILE + row * PITCH + sw * 16;
        cp16(d, (const char*)(g_w0h + (size_t)row * K0D + kt * BK) + ch * 16);
    }
    asm volatile("cp.async.commit_group;" ::: "memory");
}

__device__ __forceinline__ void gemm_epilogue(
    char* sm, int tid, int lane, int wm, int wn, int bx,
    float (*acc)[8][4], float* C, float* GS, float* GQ)
{
    float* ssum = (float*)sm;
    float* ssq  = ((float*)sm) + BN;
    if (tid < BN) { ssum[tid] = 0.f; ssq[tid] = 0.f; }
    __syncthreads();

    int rbase = bx * BM + wm * 32 + (lane >> 2);
    int cbase = wn * 64 + (lane & 3) * 2;
    #pragma unroll
    for (int mf = 0; mf < 2; ++mf)
        #pragma unroll
        for (int g = 0; g < 8; ++g) {
            *(float2*)(C + (size_t)(rbase + mf * 16) * OD + cbase + g * 8) =
                make_float2(acc[mf][g][0], acc[mf][g][1]);
            *(float2*)(C + (size_t)(rbase + mf * 16 + 8) * OD + cbase + g * 8) =
                make_float2(acc[mf][g][2], acc[mf][g][3]);
        }

    #pragma unroll
    for (int g = 0; g < 8; ++g)
        #pragma unroll
        for (int e = 0; e < 2; ++e) {
            float v0 = acc[0][g][e], v1 = acc[0][g][e + 2];
            float v2 = acc[1][g][e], v3 = acc[1][g][e + 2];
            float s = v0 + v1 + v2 + v3;
            float q = fmaf(v0, v0, fmaf(v1, v1, fmaf(v2, v2, v3 * v3)));
            #pragma unroll
            for (int m = 4; m < 32; m <<= 1) {
                s += __shfl_xor_sync(0xffffffffu, s, m);
                q += __shfl_xor_sync(0xffffffffu, q, m);
            }
            if ((lane >> 2) == 0) {
                int col = cbase + g * 8 + e;
                atomicAdd(&ssum[col], s);
                atomicAdd(&ssq[col], q);
            }
        }
    __syncthreads();
    if (tid < BN) {
        int slot = (bx & (NSLOT - 1)) * OD + tid;
        atomicAdd(&GS[slot], ssum[tid]);
        atomicAdd(&GQ[slot], ssq[tid]);
    }
}

#define COMPUTE_TILE(s0)                                                       \
    do {                                                                       \
        uint32_t ah[2][4], al[2][4];                                           \
        _Pragma("unroll")                                                      \
        for (int mf = 0; mf < 2; ++mf) {                                       \
            uint32_t aa = (s0) + a_off + mf * 16 * PITCH;                      \
            LDX4(ah[mf], aa);                                                  \
            LDX4(al[mf], aa + TILE);                                           \
        }                                                                      \
        _Pragma("unroll")                                                      \
        for (int g = 0; g < 4; ++g) {                                          \
            uint32_t ba = (s0) + 2 * TILE + b_off + g * 16 * PITCH;            \
            uint32_t bb[4];                                                    \
            LDX4(bb, ba);                                                      \
            _Pragma("unroll")                                                  \
            for (int mf = 0; mf < 2; ++mf) {                                   \
                MMA(acc[mf][2 * g],     ah[mf], bb[0], bb[2]);                 \
                MMA(acc[mf][2 * g + 1], ah[mf], bb[1], bb[3]);                 \
                MMA(acc[mf][2 * g],     al[mf], bb[0], bb[2]);                 \
                MMA(acc[mf][2 * g + 1], al[mf], bb[1], bb[3]);                 \
            }                                                                  \
        }                                                                      \
    } while (0)

__global__ __launch_bounds__(512) void k_gemm0()
{
    constexpr int KT = K0D / BK;   // 24
    __shared__ __align__(16) char sm[SMEMB];
    uint32_t sb = s2u(sm);
    int tid = threadIdx.x, bx = blockIdx.x;
    int wid = tid >> 5, lane = tid & 31;
    int wm = wid & 3, wn = wid >> 2;

    float acc[2][8][4];
    #pragma unroll
    for (int a = 0; a < 2; ++a)
        #pragma unroll
        for (int b = 0; b < 8; ++b)
            #pragma unroll
            for (int c = 0; c < 4; ++c) acc[a][b][c] = 0.f;

    uint32_t sw16 = (uint32_t)((((lane >> 4) ^ (lane >> 2)) & 1) << 4);
    uint32_t a_off = (wm * 32 + (lane & 15)) * PITCH + sw16;
    uint32_t b_off = (wn * 64 + (lane & 15)) * PITCH + sw16;

    load_stage0(sb, bx, tid, 0);
    load_stage0(sb + STAGE, bx, tid, 1);

    int st = 0;
    for (int kt = 0; kt < KT; ++kt) {
        if (kt + 1 < KT) asm volatile("cp.async.wait_group 1;" ::: "memory");
        else             asm volatile("cp.async.wait_group 0;" ::: "memory");
        __syncthreads();
        if (kt + 2 < KT) {
            int st2 = st + 2; if (st2 >= 3) st2 -= 3;
            load_stage0(sb + st2 * STAGE, bx, tid, kt + 2);
        }
        uint32_t s0 = sb + st * STAGE;
        COMPUTE_TILE(s0);
        if (++st == 3) st = 0;
    }
    __syncthreads();
    gemm_epilogue(sm, tid, lane, wm, wn, bx, acc, g_y0, g_sum0, g_sq0);
}

// ---------------- finalize BN0 stats -> g_sc0/g_sh0 -----------------------------
__global__ void k_fin0(const float* __restrict__ g, const float* __restrict__ beta) {
    int o = threadIdx.x;
    float s = 0.f, q = 0.f;
    #pragma unroll
    for (int k = 0; k < NSLOT; ++k) { s += g_sum0[k * OD + o]; q += g_sq0[k * OD + o]; }
    const float invM = 1.f / (float)M_TOT;
    float mean = s * invM;
    float var  = q * invM - mean * mean;
    float rstd = rsqrtf(var + BN_EPS);
    float sc = g[o] * rstd;
    g_sc0[o] = sc;
    g_sh0[o] = beta[o] - mean * sc;
}

// ---------------- GEMM1: A = relu(y0*sc0+sh0) fused in-kernel -------------------
__global__ __launch_bounds__(512) void k_gemm1()
{
    constexpr int KDIM = OD, KT = KDIM / BK;   // 16
    __shared__ __align__(16) char sm[SMEMB];
    uint32_t sb = s2u(sm);
    int tid = threadIdx.x, bx = blockIdx.x;
    int wid = tid >> 5, lane = tid & 31;
    int wm = wid & 3, wn = wid >> 2;

    float acc[2][8][4];
    #pragma unroll
    for (int a = 0; a < 2; ++a)
        #pragma unroll
        for (int b = 0; b < 8; ++b)
            #pragma unroll
            for (int c = 0; c < 4; ++c) acc[a][b][c] = 0.f;

    uint32_t sw16 = (uint32_t)((((lane >> 4) ^ (lane >> 2)) & 1) << 4);
    uint32_t a_off = (wm * 32 + (lane & 15)) * PITCH + sw16;
    uint32_t b_off = (wn * 64 + (lane & 15)) * PITCH + sw16;

    int arow = tid >> 2, akq = tid & 3;
    const float* ybase = g_y0 + (size_t)(bx * BM + arow) * OD + akq * 4;
    int aswz = (akq >> 1) ^ ((arow >> 2) & 1);
    uint32_t aoffb = (uint32_t)(arow * PITCH + aswz * 16 + (akq & 1) * 8);

    float4 rA0 = *(const float4*)(ybase + 0 * BK);
    float4 rA  = *(const float4*)(ybase + 1 * BK);
    {
        int c = 0 * BK + akq * 4;
        float4 s4 = *(const float4*)(g_sc0 + c);
        float4 h4 = *(const float4*)(g_sh0 + c);
        rA0.x = fmaxf(fmaf(rA0.x, s4.x, h4.x), 0.f);
        rA0.y = fmaxf(fmaf(rA0.y, s4.y, h4.y), 0.f);
        rA0.z = fmaxf(fmaf(rA0.z, s4.z, h4.z), 0.f);
        rA0.w = fmaxf(fmaf(rA0.w, s4.w, h4.w), 0.f);
        *(uint2*)(sm + aoffb)        = split_h4(rA0);
        *(uint2*)(sm + TILE + aoffb) = split_l4(rA0);
    }
    {
        int row = tid >> 1, ch = tid & 1;
        int sw = ch ^ ((row >> 2) & 1);
        uint32_t d = sb + 2 * TILE + row * PITCH + sw * 16;
        cp16(d, (const char*)(g_w1h + (size_t)row * KDIM + 0 * BK) + ch * 16);
        asm volatile("cp.async.commit_group;" ::: "memory");
        cp16(d + STAGE, (const char*)(g_w1h + (size_t)row * KDIM + 1 * BK) + ch * 16);
        asm volatile("cp.async.commit_group;" ::: "memory");
    }

    int st = 0;
    for (int kt = 0; kt < KT; ++kt) {
        if (kt + 1 < KT) asm volatile("cp.async.wait_group 1;" ::: "memory");
        else             asm volatile("cp.async.wait_group 0;" ::: "memory");
        __syncthreads();

        if (kt + 2 < KT) {
            int st2 = st + 2; if (st2 >= 3) st2 -= 3;
            {
                int row = tid >> 1, ch = tid & 1;
                int sw = ch ^ ((row >> 2) & 1);
                cp16(sb + st2 * STAGE + 2 * TILE + row * PITCH + sw * 16,
                     (const char*)(g_w1h + (size_t)row * KDIM + (kt + 2) * BK) + ch * 16);
                asm volatile("cp.async.commit_group;" ::: "memory");
            }
            float4 t = *(const float4*)(ybase + (kt + 2) * BK);
            int st1 = st + 1; if (st1 >= 3) st1 -= 3;
            int c = (kt + 1) * BK + akq * 4;
            float4 s4 = *(const float4*)(g_sc0 + c);
            float4 h4 = *(const float4*)(g_sh0 + c);
            rA.x = fmaxf(fmaf(rA.x, s4.x, h4.x), 0.f);
            rA.y = fmaxf(fmaf(rA.y, s4.y, h4.y), 0.f);
            rA.z = fmaxf(fmaf(rA.z, s4.z, h4.z), 0.f);
            rA.w = fmaxf(fmaf(rA.w, s4.w, h4.w), 0.f);
            *(uint2*)(sm + st1 * STAGE + aoffb)        = split_h4(rA);
            *(uint2*)(sm + st1 * STAGE + TILE + aoffb) = split_l4(rA);
            rA = t;
        } else if (kt + 1 < KT) {
            int st1 = st + 1; if (st1 >= 3) st1 -= 3;
            int c = (kt + 1) * BK + akq * 4;
            float4 s4 = *(const float4*)(g_sc0 + c);
            float4 h4 = *(const float4*)(g_sh0 + c);
            rA.x = fmaxf(fmaf(rA.x, s4.x, h4.x), 0.f);
            rA.y = fmaxf(fmaf(rA.y, s4.y, h4.y), 0.f);
            rA.z = fmaxf(fmaf(rA.z, s4.z, h4.z), 0.f);
            rA.w = fmaxf(fmaf(rA.w, s4.w, h4.w), 0.f);
            *(uint2*)(sm + st1 * STAGE + aoffb)        = split_h4(rA);
            *(uint2*)(sm + st1 * STAGE + TILE + aoffb) = split_l4(rA);
        }

        uint32_t s0 = sb + st * STAGE;
        COMPUTE_TILE(s0);
        if (++st == 3) st = 0;
    }
    __syncthreads();
    gemm_epilogue(sm, tid, lane, wm, wn, bx, acc, g_y1, g_sum1, g_sq1);
}

// ---------------- output: fin1 + BN1 + ReLU + transpose -------------------------
// grid (NPTS/128, OD/32, BATCH), 256 thr; each block: 128 n x 32 o.
__global__ __launch_bounds__(256) void k_out(
    float* __restrict__ out, const float* __restrict__ g1, const float* __restrict__ beta1)
{
    __shared__ float tile[32][33];
    __shared__ float s_sc[32], s_sh[32];
    int b = blockIdx.z;
    int o0 = blockIdx.y * 32, nb = blockIdx.x * 128;
    int tx = threadIdx.x & 31, ty = threadIdx.x >> 5;

    if (threadIdx.x < 32) {
        int o = o0 + threadIdx.x;
        float s = 0.f, q = 0.f;
        #pragma unroll
        for (int k = 0; k < NSLOT; ++k) { s += g_sum1[k * OD + o]; q += g_sq1[k * OD + o]; }
        const float invM = 1.f / (float)M_TOT;
        float mean = s * invM;
        float var  = q * invM - mean * mean;
        float rstd = rsqrtf(var + BN_EPS);
        float sc = g1[o] * rstd;
        s_sc[threadIdx.x] = sc;
        s_sh[threadIdx.x] = beta1[o] - mean * sc;
    }
    __syncthreads();
    float sc = s_sc[tx], sh = s_sh[tx];

    for (int nt = 0; nt < 4; ++nt) {
        int n0 = nb + nt * 32;
        #pragma unroll
        for (int i = 0; i < 32; i += 8) {
            float y = g_y1[((size_t)(b * NPTS + n0 + ty + i)) * OD + o0 + tx];
            tile[ty + i][tx] = fmaxf(fmaf(y, sc, sh), 0.f);
        }
        __syncthreads();
        #pragma unroll
        for (int i = 0; i < 32; i += 8)
            out[((size_t)b * OD + o0 + ty + i) * NPTS + n0 + tx] = tile[tx][ty + i];
        __syncthreads();
    }
}

// ---------------- launch -------------------------------------------------------
extern "C" void kernel_launch(void* const* d_in, const int* in_sizes, int n_in,
                              void* d_out, int out_size) {
    const float* xyz1    = (const float*)d_in[0];
    const float* xyz2    = (const float*)d_in[1];
    const float* points1 = (const float*)d_in[2];
    const float* points2 = (const float*)d_in[3];
    const float* W0      = (const float*)d_in[4];
    const float* g0      = (const float*)d_in[6];
    const float* beta0   = (const float*)d_in[7];
    const float* W1      = (const float*)d_in[8];
    const float* g1      = (const float*)d_in[10];
    const float* beta1   = (const float*)d_in[11];
    float* out = (float*)d_out;

    k_init<<<(OD * K0D + 255) / 256, 256>>>(W0, W1);
    k_pre<<<PRE_BLKS, 256>>>(xyz1, xyz2, points1, points2);
    k_interp<<<M_TOT / 8, 256>>>();

    k_gemm0<<<M_TOT / BM, 512>>>();
    k_fin0<<<1, OD>>>(g0, beta0);

    k_gemm1<<<M_TOT / BM, 512>>>();

    k_out<<<dim3(NPTS / 128, OD / 32, BATCH), 256>>>(out, g1, beta1);
}

// round 16
// speedup vs baseline: 1.0643x; 1.0022x over previous
#include <cuda_runtime.h>
#include <cuda_fp16.h>
#include <cstdint>

#define BATCH 8
#define NPTS  16384
#define SPTS  2048
#define C1D   128
#define C2D   256
#define K0D   384      // C1+C2
#define OD    256      // both MLP widths
#define M_TOT (BATCH*NPTS)   // 131072
#define BN_EPS 1e-5f
#define NSLOT 8

// GEMM tiling: BM=128, BN=256(=OD), BK=16, 512 threads, 3-stage, 48KB static smem
#define BM 128
#define BN 256
#define BK 16
#define PITCH 32
#define TILE  (128*PITCH)              // 4096 B
#define STAGE (4*TILE)                 // Ah,Al (2 tiles) + B 256 rows (2 tiles) = 16KB
#define SMEMB (3*STAGE)                // 49152 = 48KB

// fat pre-kernel role ranges
#define NN3_BLKS  (NPTS/256*BATCH)                 // 512
#define TP2_BLKS  ((SPTS/32)*(C2D/32)*BATCH)       // 4096
#define TP1_BLKS  ((NPTS/32)*(C1D/32)*BATCH)       // 16384
#define PRE_BLKS  (NN3_BLKS+TP2_BLKS+TP1_BLKS)

// ---------------- scratch (static device globals; no allocation) ----------------
__device__ __align__(16) float g_p2t[BATCH * SPTS * C2D];
__device__ __align__(16) float g_y0 [(size_t)M_TOT * OD];
__device__ __align__(16) float g_y1 [(size_t)M_TOT * OD];
__device__ __align__(16) __half g_a0h[(size_t)M_TOT * K0D];
__device__ __align__(16) __half g_a0l[(size_t)M_TOT * K0D];
__device__ __align__(16) __half g_w0h[OD * K0D];
__device__ __align__(16) __half g_w1h[OD * OD];
__device__ int   g_idx[M_TOT * 3];
__device__ float g_w  [M_TOT * 3];
__device__ float g_sum0[NSLOT * OD], g_sq0[NSLOT * OD];
__device__ float g_sum1[NSLOT * OD], g_sq1[NSLOT * OD];
__device__ __align__(16) float g_sc0[OD];
__device__ __align__(16) float g_sh0[OD];

// ---------------- asm helpers --------------------------------------------------
__device__ __forceinline__ uint32_t s2u(const void* p) {
    uint32_t a;
    asm("{ .reg .u64 t; cvta.to.shared.u64 t, %1; cvt.u32.u64 %0, t; }" : "=r"(a) : "l"(p));
    return a;
}
__device__ __forceinline__ void cp16(uint32_t s, const void* g) {
    asm volatile("cp.async.cg.shared.global [%0], [%1], 16;" :: "r"(s), "l"(g));
}
#define LDX4(r, addr)                                                          \
    asm volatile("ldmatrix.sync.aligned.m8n8.x4.shared.b16 {%0,%1,%2,%3}, [%4];" \
        : "=r"((r)[0]), "=r"((r)[1]), "=r"((r)[2]), "=r"((r)[3]) : "r"(addr))
#define MMA(d, a, b0, b1)                                                      \
    asm volatile("mma.sync.aligned.m16n8k16.row.col.f32.f16.f16.f32 "          \
        "{%0,%1,%2,%3}, {%4,%5,%6,%7}, {%8,%9}, {%0,%1,%2,%3};"                \
        : "+f"((d)[0]), "+f"((d)[1]), "+f"((d)[2]), "+f"((d)[3])               \
        : "r"((a)[0]), "r"((a)[1]), "r"((a)[2]), "r"((a)[3]), "r"(b0), "r"(b1))

__device__ __forceinline__ uint2 split_h4(float4 v) {
    __half2 a, b;
    a.x = __float2half_rn(v.x); a.y = __float2half_rn(v.y);
    b.x = __float2half_rn(v.z); b.y = __float2half_rn(v.w);
    uint2 r; r.x = *(uint32_t*)&a; r.y = *(uint32_t*)&b;
    return r;
}
__device__ __forceinline__ uint2 split_l4(float4 v) {
    __half hx = __float2half_rn(v.x), hy = __float2half_rn(v.y);
    __half hz = __float2half_rn(v.z), hw = __float2half_rn(v.w);
    __half2 a, b;
    a.x = __float2half_rn(v.x - __half2float(hx));
    a.y = __float2half_rn(v.y - __half2float(hy));
    b.x = __float2half_rn(v.z - __half2float(hz));
    b.y = __float2half_rn(v.w - __half2float(hw));
    uint2 r; r.x = *(uint32_t*)&a; r.y = *(uint32_t*)&b;
    return r;
}

// ---------------- kernel: zero stats + round W to fp16 (merged) -----------------
__global__ void k_init(const float* __restrict__ W0, const float* __restrict__ W1) {
    int t = blockIdx.x * blockDim.x + threadIdx.x;
    if (t < NSLOT * OD) { g_sum0[t] = 0.f; g_sq0[t] = 0.f; g_sum1[t] = 0.f; g_sq1[t] = 0.f; }
    if (t < OD * K0D) g_w0h[t] = __float2half_rn(W0[t]);
    if (t < OD * OD)  g_w1h[t] = __float2half_rn(W1[t]);
}

// ---------------- fat pre-kernel: nn3 | tr_p2 | tr_p1 ---------------------------
__device__ __forceinline__ void nn_ins(float d, int s,
    float& d0, float& d1, float& d2, int& i0, int& i1, int& i2) {
    if (d < d2) {
        if (d < d1) {
            d2 = d1; i2 = i1;
            if (d < d0) { d1 = d0; i1 = i0; d0 = d; i0 = s; }
            else        { d1 = d;  i1 = s; }
        } else { d2 = d; i2 = s; }
    }
}

__global__ __launch_bounds__(256) void k_pre(
    const float* __restrict__ xyz1, const float* __restrict__ xyz2,
    const float* __restrict__ p1,   const float* __restrict__ p2)
{
    __shared__ __align__(16) char smraw[SPTS * 16];   // 32KB: sp[2048] or tile[32][33]
    int bid = blockIdx.x, tid = threadIdx.x;

    if (bid < NN3_BLKS) {
        float4* sp = (float4*)smraw;
        int b = bid >> 6;
        const float* x2 = xyz2 + (size_t)b * SPTS * 3;
        for (int i = tid; i < SPTS * 3; i += 256) {
            int s = i / 3, d = i - 3 * s;
            ((float*)&sp[s])[d] = x2[i];
        }
        __syncthreads();

        int n = (bid & 63) * 256 + tid;
        const float* p = xyz1 + ((size_t)b * NPTS + n) * 3;
        float px = p[0], py = p[1], pz = p[2];

        float d0 = 1e30f, d1 = 1e30f, d2 = 1e30f;
        int   i0 = 0,     i1 = 0,     i2 = 0;
        #pragma unroll 1
        for (int s = 0; s < SPTS; s += 4) {
            float4 q0 = sp[s], q1 = sp[s + 1], q2 = sp[s + 2], q3 = sp[s + 3];
            float dx = px - q0.x, dy = py - q0.y, dz = pz - q0.z;
            float da = fmaf(dx, dx, fmaf(dy, dy, dz * dz));
            dx = px - q1.x; dy = py - q1.y; dz = pz - q1.z;
            float db = fmaf(dx, dx, fmaf(dy, dy, dz * dz));
            dx = px - q2.x; dy = py - q2.y; dz = pz - q2.z;
            float dc = fmaf(dx, dx, fmaf(dy, dy, dz * dz));
            dx = px - q3.x; dy = py - q3.y; dz = pz - q3.z;
            float dd = fmaf(dx, dx, fmaf(dy, dy, dz * dz));
            float mn = fminf(fminf(da, db), fminf(dc, dd));
            if (mn < d2) {
                nn_ins(da, s,     d0, d1, d2, i0, i1, i2);
                nn_ins(db, s + 1, d0, d1, d2, i0, i1, i2);
                nn_ins(dc, s + 2, d0, d1, d2, i0, i1, i2);
                nn_ins(dd, s + 3, d0, d1, d2, i0, i1, i2);
            }
        }
        d0 = fmaxf(d0, 1e-10f); d1 = fmaxf(d1, 1e-10f); d2 = fmaxf(d2, 1e-10f);
        float w0 = 1.f / d0, w1 = 1.f / d1, w2 = 1.f / d2;
        float inv = 1.f / (w0 + w1 + w2);
        int base = ((b * NPTS) + n) * 3;
        g_idx[base] = i0; g_idx[base + 1] = i1; g_idx[base + 2] = i2;
        g_w[base] = w0 * inv; g_w[base + 1] = w1 * inv; g_w[base + 2] = w2 * inv;
    } else if (bid < NN3_BLKS + TP2_BLKS) {
        float (*tile)[33] = (float(*)[33])smraw;
        int q = bid - NN3_BLKS;
        int s0 = (q & 63) * 32;
        int c0 = ((q >> 6) & 7) * 32;
        int b  = q >> 9;
        int tx = tid & 31, ty = tid >> 5;
        #pragma unroll
        for (int i = 0; i < 32; i += 8)
            tile[ty + i][tx] = p2[((size_t)(b * C2D + c0 + ty + i)) * SPTS + s0 + tx];
        __syncthreads();
        #pragma unroll
        for (int i = 0; i < 32; i += 8)
            g_p2t[((size_t)(b * SPTS + s0 + ty + i)) * C2D + c0 + tx] = tile[tx][ty + i];
    } else {
        float (*tile)[33] = (float(*)[33])smraw;
        int q = bid - NN3_BLKS - TP2_BLKS;
        int n0 = (q & 511) * 32;
        int c0 = ((q >> 9) & 3) * 32;
        int b  = q >> 11;
        int tx = tid & 31, ty = tid >> 5;
        #pragma unroll
        for (int i = 0; i < 32; i += 8)
            tile[ty + i][tx] = p1[((size_t)(b * C1D + c0 + ty + i)) * NPTS + n0 + tx];
        __syncthreads();
        #pragma unroll
        for (int i = 0; i < 32; i += 8) {
            float v = tile[tx][ty + i];
            __half h = __float2half_rn(v);
            size_t off = ((size_t)(b * NPTS + n0 + ty + i)) * K0D + C2D + c0 + tx;
            g_a0h[off] = h;
            g_a0l[off] = __float2half_rn(v - __half2float(h));
        }
    }
}

// ---------------- interp -> a0 cols [0,256) as split fp16 ----------------------
__global__ void k_interp() {
    int gwarp = (blockIdx.x * blockDim.x + threadIdx.x) >> 5;
    int lane  = threadIdx.x & 31;
    int b = gwarp >> 14;
    int base = gwarp * 3;
    int i0 = g_idx[base], i1 = g_idx[base + 1], i2 = g_idx[base + 2];
    float w0 = g_w[base], w1 = g_w[base + 1], w2 = g_w[base + 2];
    const float4* r0 = (const float4*)(g_p2t + ((size_t)b * SPTS + i0) * C2D);
    const float4* r1 = (const float4*)(g_p2t + ((size_t)b * SPTS + i1) * C2D);
    const float4* r2 = (const float4*)(g_p2t + ((size_t)b * SPTS + i2) * C2D);
    uint2* hrow = (uint2*)(g_a0h + (size_t)gwarp * K0D);
    uint2* lrow = (uint2*)(g_a0l + (size_t)gwarp * K0D);
    #pragma unroll
    for (int c = lane; c < C2D / 4; c += 32) {
        float4 a = r0[c], bb = r1[c], cc = r2[c], o;
        o.x = w0 * a.x + w1 * bb.x + w2 * cc.x;
        o.y = w0 * a.y + w1 * bb.y + w2 * cc.y;
        o.z = w0 * a.z + w1 * bb.z + w2 * cc.z;
        o.w = w0 * a.w + w1 * bb.w + w2 * cc.w;
        hrow[c] = split_h4(o);
        lrow[c] = split_l4(o);
    }
}

// ---------------- GEMM pieces ---------------------------------------------------
__device__ __forceinline__ void load_stage0(
    uint32_t s0, int bx, int tid, int kt)
{
    {
        int hsel = tid >> 8;
        int q = tid & 255;
        int row = q >> 1, ch = q & 1;
        int sw = ch ^ ((row >> 2) & 1);
        uint32_t d = s0 + hsel * TILE + row * PITCH + sw * 16;
        const __half* src = hsel ? g_a0l : g_a0h;
        cp16(d, (const char*)(src + (size_t)(bx * BM + row) * K0D + kt * BK) + ch * 16);
    }
    {
        int row = tid >> 1, ch = tid & 1;
        int sw = ch ^ ((row >> 2) & 1);
        uint32_t d = s0 + 2 * TILE + row * PITCH + sw * 16;
        cp16(d, (const char*)(g_w0h + (size_t)row * K0D + kt * BK) + ch * 16);
    }
    asm volatile("cp.async.commit_group;" ::: "memory");
}

__device__ __forceinline__ void gemm_epilogue(
    char* sm, int tid, int lane, int wm, int wn, int bx,
    float (*acc)[8][4], float* C, float* GS, float* GQ)
{
    float* ssum = (float*)sm;
    float* ssq  = ((float*)sm) + BN;
    if (tid < BN) { ssum[tid] = 0.f; ssq[tid] = 0.f; }
    __syncthreads();

    int rbase = bx * BM + wm * 32 + (lane >> 2);
    int cbase = wn * 64 + (lane & 3) * 2;
    #pragma unroll
    for (int mf = 0; mf < 2; ++mf)
        #pragma unroll
        for (int g = 0; g < 8; ++g) {
            *(float2*)(C + (size_t)(rbase + mf * 16) * OD + cbase + g * 8) =
                make_float2(acc[mf][g][0], acc[mf][g][1]);
            *(float2*)(C + (size_t)(rbase + mf * 16 + 8) * OD + cbase + g * 8) =
                make_float2(acc[mf][g][2], acc[mf][g][3]);
        }

    #pragma unroll
    for (int g = 0; g < 8; ++g)
        #pragma unroll
        for (int e = 0; e < 2; ++e) {
            float v0 = acc[0][g][e], v1 = acc[0][g][e + 2];
            float v2 = acc[1][g][e], v3 = acc[1][g][e + 2];
            float s = v0 + v1 + v2 + v3;
            float q = fmaf(v0, v0, fmaf(v1, v1, fmaf(v2, v2, v3 * v3)));
            #pragma unroll
            for (int m = 4; m < 32; m <<= 1) {
                s += __shfl_xor_sync(0xffffffffu, s, m);
                q += __shfl_xor_sync(0xffffffffu, q, m);
            }
            if ((lane >> 2) == 0) {
                int col = cbase + g * 8 + e;
                atomicAdd(&ssum[col], s);
                atomicAdd(&ssq[col], q);
            }
        }
    __syncthreads();
    if (tid < BN) {
        int slot = (bx & (NSLOT - 1)) * OD + tid;
        atomicAdd(&GS[slot], ssum[tid]);
        atomicAdd(&GQ[slot], ssq[tid]);
    }
}

// Dependency-separated compute: all fragments loaded first; pass 1 issues 16
// MMAs on 16 DISTINCT accumulators (zero RAW), pass 2 (al) reuses each acc at
// distance 16. Per-accumulator op order unchanged (ah-term then al-term).
#define COMPUTE_TILE(s0)                                                       \
    do {                                                                       \
        uint32_t ah[2][4], al[2][4], bbf[4][4];                                \
        _Pragma("unroll")                                                      \
        for (int mf = 0; mf < 2; ++mf) {                                       \
            uint32_t aa = (s0) + a_off + mf * 16 * PITCH;                      \
            LDX4(ah[mf], aa);                                                  \
            LDX4(al[mf], aa + TILE);                                           \
        }                                                                      \
        _Pragma("unroll")                                                      \
        for (int g = 0; g < 4; ++g)                                            \
            LDX4(bbf[g], (s0) + 2 * TILE + b_off + g * 16 * PITCH);            \
        _Pragma("unroll")                                                      \
        for (int g = 0; g < 4; ++g)                                            \
            _Pragma("unroll")                                                  \
            for (int mf = 0; mf < 2; ++mf) {                                   \
                MMA(acc[mf][2 * g],     ah[mf], bbf[g][0], bbf[g][2]);         \
                MMA(acc[mf][2 * g + 1], ah[mf], bbf[g][1], bbf[g][3]);         \
            }                                                                  \
        _Pragma("unroll")                                                      \
        for (int g = 0; g < 4; ++g)                                            \
            _Pragma("unroll")                                                  \
            for (int mf = 0; mf < 2; ++mf) {                                   \
                MMA(acc[mf][2 * g],     al[mf], bbf[g][0], bbf[g][2]);         \
                MMA(acc[mf][2 * g + 1], al[mf], bbf[g][1], bbf[g][3]);         \
            }                                                                  \
    } while (0)

__global__ __launch_bounds__(512) void k_gemm0()
{
    constexpr int KT = K0D / BK;   // 24
    __shared__ __align__(16) char sm[SMEMB];
    uint32_t sb = s2u(sm);
    int tid = threadIdx.x, bx = blockIdx.x;
    int wid = tid >> 5, lane = tid & 31;
    int wm = wid & 3, wn = wid >> 2;

    float acc[2][8][4];
    #pragma unroll
    for (int a = 0; a < 2; ++a)
        #pragma unroll
        for (int b = 0; b < 8; ++b)
            #pragma unroll
            for (int c = 0; c < 4; ++c) acc[a][b][c] = 0.f;

    uint32_t sw16 = (uint32_t)((((lane >> 4) ^ (lane >> 2)) & 1) << 4);
    uint32_t a_off = (wm * 32 + (lane & 15)) * PITCH + sw16;
    uint32_t b_off = (wn * 64 + (lane & 15)) * PITCH + sw16;

    load_stage0(sb, bx, tid, 0);
    load_stage0(sb + STAGE, bx, tid, 1);

    int st = 0;
    for (int kt = 0; kt < KT; ++kt) {
        if (kt + 1 < KT) asm volatile("cp.async.wait_group 1;" ::: "memory");
        else             asm volatile("cp.async.wait_group 0;" ::: "memory");
        __syncthreads();
        if (kt + 2 < KT) {
            int st2 = st + 2; if (st2 >= 3) st2 -= 3;
            load_stage0(sb + st2 * STAGE, bx, tid, kt + 2);
        }
        uint32_t s0 = sb + st * STAGE;
        COMPUTE_TILE(s0);
        if (++st == 3) st = 0;
    }
    __syncthreads();
    gemm_epilogue(sm, tid, lane, wm, wn, bx, acc, g_y0, g_sum0, g_sq0);
}

// ---------------- finalize BN0 stats -> g_sc0/g_sh0 -----------------------------
__global__ void k_fin0(const float* __restrict__ g, const float* __restrict__ beta) {
    int o = threadIdx.x;
    float s = 0.f, q = 0.f;
    #pragma unroll
    for (int k = 0; k < NSLOT; ++k) { s += g_sum0[k * OD + o]; q += g_sq0[k * OD + o]; }
    const float invM = 1.f / (float)M_TOT;
    float mean = s * invM;
    float var  = q * invM - mean * mean;
    float rstd = rsqrtf(var + BN_EPS);
    float sc = g[o] * rstd;
    g_sc0[o] = sc;
    g_sh0[o] = beta[o] - mean * sc;
}

// ---------------- GEMM1: A = relu(y0*sc0+sh0) fused in-kernel -------------------
__global__ __launch_bounds__(512) void k_gemm1()
{
    constexpr int KDIM = OD, KT = KDIM / BK;   // 16
    __shared__ __align__(16) char sm[SMEMB];
    uint32_t sb = s2u(sm);
    int tid = threadIdx.x, bx = blockIdx.x;
    int wid = tid >> 5, lane = tid & 31;
    int wm = wid & 3, wn = wid >> 2;

    float acc[2][8][4];
    #pragma unroll
    for (int a = 0; a < 2; ++a)
        #pragma unroll
        for (int b = 0; b < 8; ++b)
            #pragma unroll
            for (int c = 0; c < 4; ++c) acc[a][b][c] = 0.f;

    uint32_t sw16 = (uint32_t)((((lane >> 4) ^ (lane >> 2)) & 1) << 4);
    uint32_t a_off = (wm * 32 + (lane & 15)) * PITCH + sw16;
    uint32_t b_off = (wn * 64 + (lane & 15)) * PITCH + sw16;

    int arow = tid >> 2, akq = tid & 3;
    const float* ybase = g_y0 + (size_t)(bx * BM + arow) * OD + akq * 4;
    int aswz = (akq >> 1) ^ ((arow >> 2) & 1);
    uint32_t aoffb = (uint32_t)(arow * PITCH + aswz * 16 + (akq & 1) * 8);

    float4 rA0 = *(const float4*)(ybase + 0 * BK);
    float4 rA  = *(const float4*)(ybase + 1 * BK);
    {
        int c = 0 * BK + akq * 4;
        float4 s4 = *(const float4*)(g_sc0 + c);
        float4 h4 = *(const float4*)(g_sh0 + c);
        rA0.x = fmaxf(fmaf(rA0.x, s4.x, h4.x), 0.f);
        rA0.y = fmaxf(fmaf(rA0.y, s4.y, h4.y), 0.f);
        rA0.z = fmaxf(fmaf(rA0.z, s4.z, h4.z), 0.f);
        rA0.w = fmaxf(fmaf(rA0.w, s4.w, h4.w), 0.f);
        *(uint2*)(sm + aoffb)        = split_h4(rA0);
        *(uint2*)(sm + TILE + aoffb) = split_l4(rA0);
    }
    {
        int row = tid >> 1, ch = tid & 1;
        int sw = ch ^ ((row >> 2) & 1);
        uint32_t d = sb + 2 * TILE + row * PITCH + sw * 16;
        cp16(d, (const char*)(g_w1h + (size_t)row * KDIM + 0 * BK) + ch * 16);
        asm volatile("cp.async.commit_group;" ::: "memory");
        cp16(d + STAGE, (const char*)(g_w1h + (size_t)row * KDIM + 1 * BK) + ch * 16);
        asm volatile("cp.async.commit_group;" ::: "memory");
    }

    int st = 0;
    for (int kt = 0; kt < KT; ++kt) {
        if (kt + 1 < KT) asm volatile("cp.async.wait_group 1;" ::: "memory");
        else             asm volatile("cp.async.wait_group 0;" ::: "memory");
        __syncthreads();

        if (kt + 2 < KT) {
            int st2 = st + 2; if (st2 >= 3) st2 -= 3;
            {
                int row = tid >> 1, ch = tid & 1;
                int sw = ch ^ ((row >> 2) & 1);
                cp16(sb + st2 * STAGE + 2 * TILE + row * PITCH + sw * 16,
                     (const char*)(g_w1h + (size_t)row * KDIM + (kt + 2) * BK) + ch * 16);
                asm volatile("cp.async.commit_group;" ::: "memory");
            }
            float4 t = *(const float4*)(ybase + (kt + 2) * BK);
            int st1 = st + 1; if (st1 >= 3) st1 -= 3;
            int c = (kt + 1) * BK + akq * 4;
            float4 s4 = *(const float4*)(g_sc0 + c);
            float4 h4 = *(const float4*)(g_sh0 + c);
            rA.x = fmaxf(fmaf(rA.x, s4.x, h4.x), 0.f);
            rA.y = fmaxf(fmaf(rA.y, s4.y, h4.y), 0.f);
            rA.z = fmaxf(fmaf(rA.z, s4.z, h4.z), 0.f);
            rA.w = fmaxf(fmaf(rA.w, s4.w, h4.w), 0.f);
            *(uint2*)(sm + st1 * STAGE + aoffb)        = split_h4(rA);
            *(uint2*)(sm + st1 * STAGE + TILE + aoffb) = split_l4(rA);
            rA = t;
        } else if (kt + 1 < KT) {
            int st1 = st + 1; if (st1 >= 3) st1 -= 3;
            int c = (kt + 1) * BK + akq * 4;
            float4 s4 = *(const float4*)(g_sc0 + c);
            float4 h4 = *(const float4*)(g_sh0 + c);
            rA.x = fmaxf(fmaf(rA.x, s4.x, h4.x), 0.f);
            rA.y = fmaxf(fmaf(rA.y, s4.y, h4.y), 0.f);
            rA.z = fmaxf(fmaf(rA.z, s4.z, h4.z), 0.f);
            rA.w = fmaxf(fmaf(rA.w, s4.w, h4.w), 0.f);
            *(uint2*)(sm + st1 * STAGE + aoffb)        = split_h4(rA);
            *(uint2*)(sm + st1 * STAGE + TILE + aoffb) = split_l4(rA);
        }

        uint32_t s0 = sb + st * STAGE;
        COMPUTE_TILE(s0);
        if (++st == 3) st = 0;
    }
    __syncthreads();
    gemm_epilogue(sm, tid, lane, wm, wn, bx, acc, g_y1, g_sum1, g_sq1);
}

// ---------------- output: fin1 + BN1 + ReLU + transpose -------------------------
__global__ __launch_bounds__(256) void k_out(
    float* __restrict__ out, const float* __restrict__ g1, const float* __restrict__ beta1)
{
    __shared__ float tile[32][33];
    __shared__ float s_sc[32], s_sh[32];
    int b = blockIdx.z;
    int o0 = blockIdx.y * 32, nb = blockIdx.x * 128;
    int tx = threadIdx.x & 31, ty = threadIdx.x >> 5;

    if (threadIdx.x < 32) {
        int o = o0 + threadIdx.x;
        float s = 0.f, q = 0.f;
        #pragma unroll
        for (int k = 0; k < NSLOT; ++k) { s += g_sum1[k * OD + o]; q += g_sq1[k * OD + o]; }
        const float invM = 1.f / (float)M_TOT;
        float mean = s * invM;
        float var  = q * invM - mean * mean;
        float rstd = rsqrtf(var + BN_EPS);
        float sc = g1[o] * rstd;
        s_sc[threadIdx.x] = sc;
        s_sh[threadIdx.x] = beta1[o] - mean * sc;
    }
    __syncthreads();
    float sc = s_sc[tx], sh = s_sh[tx];

    for (int nt = 0; nt < 4; ++nt) {
        int n0 = nb + nt * 32;
        #pragma unroll
        for (int i = 0; i < 32; i += 8) {
            float y = g_y1[((size_t)(b * NPTS + n0 + ty + i)) * OD + o0 + tx];
            tile[ty + i][tx] = fmaxf(fmaf(y, sc, sh), 0.f);
        }
        __syncthreads();
        #pragma unroll
        for (int i = 0; i < 32; i += 8)
            out[((size_t)b * OD + o0 + ty + i) * NPTS + n0 + tx] = tile[tx][ty + i];
        __syncthreads();
    }
}

// ---------------- launch -------------------------------------------------------
extern "C" void kernel_launch(void* const* d_in, const int* in_sizes, int n_in,
                              void* d_out, int out_size) {
    const float* xyz1    = (const float*)d_in[0];
    const float* xyz2    = (const float*)d_in[1];
    const float* points1 = (const float*)d_in[2];
    const float* points2 = (const float*)d_in[3];
    const float* W0      = (const float*)d_in[4];
    const float* g0      = (const float*)d_in[6];
    const float* beta0   = (const float*)d_in[7];
    const float* W1      = (const float*)d_in[8];
    const float* g1      = (const float*)d_in[10];
    const float* beta1   = (const float*)d_in[11];
    float* out = (float*)d_out;

    k_init<<<(OD * K0D + 255) / 256, 256>>>(W0, W1);
    k_pre<<<PRE_BLKS, 256>>>(xyz1, xyz2, points1, points2);
    k_interp<<<M_TOT / 8, 256>>>();

    k_gemm0<<<M_TOT / BM, 512>>>();
    k_fin0<<<1, OD>>>(g0, beta0);

    k_gemm1<<<M_TOT / BM, 512>>>();

    k_out<<<dim3(NPTS / 128, OD / 32, BATCH), 256>>>(out, g1, beta1);
}